// round 1
// baseline (speedup 1.0000x reference)
#include <cuda_runtime.h>
#include <math.h>

// ---------------- problem constants ----------------
constexpr int BATCH = 2, HH = 128, WW = 128, CH = 256;
constexpr int HEADS = 8, HD = 32, WSZ = 8, KWIN = 16;
constexpr int NPIX = BATCH * HH * WW;   // 32768
constexpr int C3 = 3 * CH;              // 768
constexpr int NREL = 23 * 23;           // 529

// ---------------- device scratch (allocation-free) ----------------
__device__ float g_qkv[NPIX * C3];      // 100.7 MB
__device__ float g_qn [NPIX * CH];      // 33.5 MB  (l2-normalized * scale)
__device__ float g_kn [NPIX * CH];      // 33.5 MB  (l2-normalized)
__device__ float g_v  [NPIX * CH];      // 33.5 MB
__device__ float g_att[NPIX * CH];      // 33.5 MB
__device__ float g_btab[NREL * HEADS];  // 16.9 KB

// ---------------- CPB relative-bias MLP ----------------
__device__ __forceinline__ float relcoord(int r) {
    // coords = arange(1-WS-halo, WS+halo) = [-11..11]; *8/7; sign*log1p(|.|)/log(8)
    float cs = (float)(r - 11) * (8.0f / 7.0f);
    float a = log1pf(fabsf(cs)) * (1.0f / 2.0794415416798357f);
    return cs > 0.0f ? a : (cs < 0.0f ? -a : 0.0f);
}

__global__ void cpb_kernel(const float* __restrict__ w1, const float* __restrict__ b1,
                           const float* __restrict__ w2, float* __restrict__ btab) {
    int i = blockIdx.x;                 // 0..528
    float y0 = relcoord(i / 23), y1 = relcoord(i % 23);
    int t = threadIdx.x;                // 256 threads
    float part[HEADS];
#pragma unroll
    for (int hh = 0; hh < HEADS; hh++) part[hh] = 0.0f;
    for (int j = t; j < 512; j += 256) {
        float hv = fmaf(y0, w1[j], fmaf(y1, w1[512 + j], b1[j]));
        hv = fmaxf(hv, 0.0f);
#pragma unroll
        for (int hh = 0; hh < HEADS; hh++) part[hh] = fmaf(hv, w2[j * HEADS + hh], part[hh]);
    }
#pragma unroll
    for (int hh = 0; hh < HEADS; hh++)
#pragma unroll
        for (int o = 16; o; o >>= 1) part[hh] += __shfl_xor_sync(0xffffffffu, part[hh], o);
    __shared__ float sm[HEADS][8];
    int lane = t & 31, wrp = t >> 5;
    if (lane == 0)
        for (int hh = 0; hh < HEADS; hh++) sm[hh][wrp] = part[hh];
    __syncthreads();
    if (t < HEADS) {
        float ssum = 0.0f;
        for (int k = 0; k < 8; k++) ssum += sm[t][k];
        btab[i * HEADS + t] = 16.0f / (1.0f + expf(-ssum));
    }
}

// ---------------- fp32 SGEMM: C[M,N] = A[M,K] @ B[K,N], all row-major ----------------
// BM=BN=128, BK=8, 256 threads, 8x8 per-thread microtile. M,N divisible by 128; K by 8.
__global__ __launch_bounds__(256) void sgemm128(int M, int N, int K,
                                                const float* __restrict__ A,
                                                const float* __restrict__ B,
                                                float* __restrict__ C) {
    constexpr int BM = 128, BN = 128, BK = 8, TM = 8, TN = 8;
    __shared__ float As[BK][BM];
    __shared__ float Bs[BK][BN];
    int block_row = blockIdx.y, block_col = blockIdx.x;
    int tid = threadIdx.x;
    int tRow = tid / (BN / TN);          // 0..15
    int tCol = tid % (BN / TN);          // 0..15
    int aRow = tid >> 1;                 // 0..127
    int aCol = (tid & 1) << 2;           // 0 or 4
    int bRow = tid >> 5;                 // 0..7
    int bCol = (tid & 31) << 2;          // 0..124
    const float* Ab = A + (size_t)block_row * BM * K;
    const float* Bb = B + (size_t)block_col * BN;
    float acc[TM][TN];
#pragma unroll
    for (int i = 0; i < TM; i++)
#pragma unroll
        for (int j = 0; j < TN; j++) acc[i][j] = 0.0f;
    float ra[TM], rb[TN];
    for (int k0 = 0; k0 < K; k0 += BK) {
        float4 a4 = *(const float4*)(Ab + (size_t)aRow * K + k0 + aCol);
        As[aCol + 0][aRow] = a4.x; As[aCol + 1][aRow] = a4.y;
        As[aCol + 2][aRow] = a4.z; As[aCol + 3][aRow] = a4.w;
        float4 b4 = *(const float4*)(Bb + (size_t)(k0 + bRow) * N + bCol);
        *(float4*)(&Bs[bRow][bCol]) = b4;
        __syncthreads();
#pragma unroll
        for (int kk = 0; kk < BK; kk++) {
#pragma unroll
            for (int i = 0; i < TM; i++) ra[i] = As[kk][tRow * TM + i];
#pragma unroll
            for (int j = 0; j < TN; j++) rb[j] = Bs[kk][tCol * TN + j];
#pragma unroll
            for (int i = 0; i < TM; i++)
#pragma unroll
                for (int j = 0; j < TN; j++) acc[i][j] = fmaf(ra[i], rb[j], acc[i][j]);
        }
        __syncthreads();
    }
    float* Cb = C + (size_t)block_row * BM * N + block_col * BN;
#pragma unroll
    for (int i = 0; i < TM; i++) {
#pragma unroll
        for (int j = 0; j < TN; j += 4) {
            float4 v = {acc[i][j], acc[i][j + 1], acc[i][j + 2], acc[i][j + 3]};
            *(float4*)(Cb + (size_t)(tRow * TM + i) * N + tCol * TN + j) = v;
        }
    }
}

// ---------------- depthwise 3x3 conv + LayerNorm + biases + l2norm + logit scale ----------------
// one block per pixel, 768 threads (thread c == channel c; warp == one head for c<512)
__global__ __launch_bounds__(768) void conv_ln_kernel(
    const float* __restrict__ qkv, const float* __restrict__ wdw,
    const float* __restrict__ ln_g, const float* __restrict__ ln_b,
    const float* __restrict__ q_bias, const float* __restrict__ v_bias,
    const float* __restrict__ logit_scale,
    float* __restrict__ qn, float* __restrict__ kn, float* __restrict__ vv) {
    int p = blockIdx.x;
    int b = p >> 14, y = (p >> 7) & 127, x = p & 127;
    int c = threadIdx.x;
    float acc = 0.0f;
#pragma unroll
    for (int dy = -1; dy <= 1; dy++) {
        int yy = y + dy;
        if ((unsigned)yy >= (unsigned)HH) continue;
#pragma unroll
        for (int dx = -1; dx <= 1; dx++) {
            int xx = x + dx;
            if ((unsigned)xx >= (unsigned)WW) continue;
            acc = fmaf(qkv[(size_t)(((b << 7) | yy) << 7 | xx) * C3 + c],
                       wdw[((dy + 1) * 3 + (dx + 1)) * C3 + c], acc);
        }
    }
    // block reduction: mean & var over 768 channels
    float s = acc, s2 = acc * acc;
#pragma unroll
    for (int o = 16; o; o >>= 1) {
        s  += __shfl_xor_sync(0xffffffffu, s, o);
        s2 += __shfl_xor_sync(0xffffffffu, s2, o);
    }
    __shared__ float ws[24], ws2[24];
    __shared__ float s_mu, s_rstd;
    int lane = c & 31, wrp = c >> 5;
    if (lane == 0) { ws[wrp] = s; ws2[wrp] = s2; }
    __syncthreads();
    if (c < 32) {
        float a  = (c < 24) ? ws[c]  : 0.0f;
        float a2 = (c < 24) ? ws2[c] : 0.0f;
#pragma unroll
        for (int o = 16; o; o >>= 1) {
            a  += __shfl_xor_sync(0xffffffffu, a, o);
            a2 += __shfl_xor_sync(0xffffffffu, a2, o);
        }
        if (c == 0) {
            float mu = a * (1.0f / 768.0f);
            float var = a2 * (1.0f / 768.0f) - mu * mu;
            s_mu = mu;
            s_rstd = rsqrtf(var + 1e-5f);
        }
    }
    __syncthreads();
    float val = (acc - s_mu) * s_rstd * ln_g[c] + ln_b[c];
    if (c < 256) {
        val += q_bias[c];
        float ss = val * val;
#pragma unroll
        for (int o = 16; o; o >>= 1) ss += __shfl_xor_sync(0xffffffffu, ss, o);
        float rn = rsqrtf(fmaxf(ss, 1.55e-5f));
        float sc = __expf(fminf(logit_scale[c >> 5], 4.6051701859880914f)); // ln(100)
        qn[(size_t)p * CH + c] = val * rn * sc;
    } else if (c < 512) {
        float ss = val * val;
#pragma unroll
        for (int o = 16; o; o >>= 1) ss += __shfl_xor_sync(0xffffffffu, ss, o);
        kn[(size_t)p * CH + (c - 256)] = val * rsqrtf(fmaxf(ss, 1.55e-5f));
    } else {
        vv[(size_t)p * CH + (c - 512)] = val + v_bias[c - 512];
    }
}

// ---------------- windowed attention with online softmax ----------------
// grid (512 windows, 8 heads), 256 threads: 4 threads per query (8 dims each)
__global__ __launch_bounds__(256) void attn_kernel(
    const float* __restrict__ qn, const float* __restrict__ kn,
    const float* __restrict__ vv, const float* __restrict__ btab,
    float* __restrict__ out) {
    __shared__ float ks[64 * 32];
    __shared__ float vs[64 * 32];
    __shared__ float bsm[NREL];
    int w = blockIdx.x, h = blockIdx.y;
    int b = w >> 8, wr = (w >> 4) & 15, wc = w & 15;
    int tid = threadIdx.x;
    int q = tid >> 2, sub = tid & 3;
    int qi = q >> 3, qj = q & 7;
    for (int i = tid; i < NREL; i += 256) bsm[i] = btab[i * HEADS + h];
    int py = wr * 8 + qi, px = wc * 8 + qj;
    const float* qptr = qn + (size_t)(((b << 7) | py) << 7 | px) * CH + h * HD + sub * 8;
    float qr[8];
    {
        float4 qa = *(const float4*)qptr;
        float4 qb = *(const float4*)(qptr + 4);
        qr[0] = qa.x; qr[1] = qa.y; qr[2] = qa.z; qr[3] = qa.w;
        qr[4] = qb.x; qr[5] = qb.y; qr[6] = qb.z; qr[7] = qb.w;
    }
    float m = -INFINITY, l = 0.0f, acc[8];
#pragma unroll
    for (int i = 0; i < 8; i++) acc[i] = 0.0f;
    int lkey = tid >> 2;   // local key row this thread helps load
    for (int c0 = 0; c0 < 4; c0++) {
        int j = c0 * 64 + lkey;
        int kr = j >> 4, kc = j & 15;
        int gy = wr * 8 - 4 + kr, gx = wc * 8 - 4 + kc;
        float4 k0 = {0, 0, 0, 0}, k1 = {0, 0, 0, 0}, v0 = {0, 0, 0, 0}, v1 = {0, 0, 0, 0};
        if ((unsigned)gy < 128u && (unsigned)gx < 128u) {
            size_t gbase = (size_t)(((b << 7) | gy) << 7 | gx) * CH + h * HD + sub * 8;
            k0 = *(const float4*)(kn + gbase); k1 = *(const float4*)(kn + gbase + 4);
            v0 = *(const float4*)(vv + gbase); v1 = *(const float4*)(vv + gbase + 4);
        }
        __syncthreads();   // prior chunk's compute done before overwrite (also fences bsm fill on c0==0)
        *(float4*)&ks[lkey * 32 + sub * 8] = k0; *(float4*)&ks[lkey * 32 + sub * 8 + 4] = k1;
        *(float4*)&vs[lkey * 32 + sub * 8] = v0; *(float4*)&vs[lkey * 32 + sub * 8 + 4] = v1;
        __syncthreads();
        int kb0 = c0 * 64;
#pragma unroll 4
        for (int jj = 0; jj < 64; jj++) {
            int jg = kb0 + jj;
            int kr2 = jg >> 4, kc2 = jg & 15;
            const float* kp = &ks[jj * 32 + sub * 8];
            float sdot = 0.0f;
#pragma unroll
            for (int i = 0; i < 8; i++) sdot = fmaf(qr[i], kp[i], sdot);
            sdot += __shfl_xor_sync(0xffffffffu, sdot, 1);
            sdot += __shfl_xor_sync(0xffffffffu, sdot, 2);
            float sv = sdot + bsm[(qi - kr2 + 15) * 23 + (qj - kc2 + 15)];
            // single-exp online softmax update
            float mn = fmaxf(m, sv);
            float e = __expf(fminf(m, sv) - mn);       // exp(-inf)=0 handles first key
            bool snew = sv > m;
            float corr = snew ? e : 1.0f;
            float pp   = snew ? 1.0f : e;
            m = mn;
            l = fmaf(l, corr, pp);
            const float* vp2 = &vs[jj * 32 + sub * 8];
#pragma unroll
            for (int i = 0; i < 8; i++) acc[i] = fmaf(acc[i], corr, pp * vp2[i]);
        }
    }
    float inv = 1.0f / l;
    float* op = out + (size_t)(((b << 7) | py) << 7 | px) * CH + h * HD + sub * 8;
    float4 o0 = {acc[0] * inv, acc[1] * inv, acc[2] * inv, acc[3] * inv};
    float4 o1 = {acc[4] * inv, acc[5] * inv, acc[6] * inv, acc[7] * inv};
    *(float4*)op = o0;
    *(float4*)(op + 4) = o1;
}

// ---------------- launch ----------------
extern "C" void kernel_launch(void* const* d_in, const int* in_sizes, int n_in,
                              void* d_out, int out_size) {
    const float* x           = (const float*)d_in[0];
    const float* w_qkv       = (const float*)d_in[1];
    const float* w_dw        = (const float*)d_in[2];
    const float* ln_g        = (const float*)d_in[3];
    const float* ln_b        = (const float*)d_in[4];
    const float* q_bias      = (const float*)d_in[5];
    const float* v_bias      = (const float*)d_in[6];
    const float* logit_scale = (const float*)d_in[7];
    const float* cpb_w1      = (const float*)d_in[8];
    const float* cpb_b1      = (const float*)d_in[9];
    const float* cpb_w2      = (const float*)d_in[10];
    const float* w_proj      = (const float*)d_in[11];
    float* out = (float*)d_out;

    float *qkv, *qn, *kn, *vv, *att, *btab;
    cudaGetSymbolAddress((void**)&qkv,  g_qkv);
    cudaGetSymbolAddress((void**)&qn,   g_qn);
    cudaGetSymbolAddress((void**)&kn,   g_kn);
    cudaGetSymbolAddress((void**)&vv,   g_v);
    cudaGetSymbolAddress((void**)&att,  g_att);
    cudaGetSymbolAddress((void**)&btab, g_btab);

    cpb_kernel<<<NREL, 256>>>(cpb_w1, cpb_b1, cpb_w2, btab);
    sgemm128<<<dim3(C3 / 128, NPIX / 128), 256>>>(NPIX, C3, CH, x, w_qkv, qkv);
    conv_ln_kernel<<<NPIX, 768>>>(qkv, w_dw, ln_g, ln_b, q_bias, v_bias, logit_scale,
                                  qn, kn, vv);
    attn_kernel<<<dim3(512, 8), 256>>>(qn, kn, vv, btab, att);
    sgemm128<<<dim3(CH / 128, NPIX / 128), 256>>>(NPIX, CH, CH, att, w_proj, out);
}

// round 2
// speedup vs baseline: 1.2881x; 1.2881x over previous
#include <cuda_runtime.h>
#include <math.h>

// ---------------- problem constants ----------------
constexpr int BATCH = 2, HH = 128, WW = 128, CH = 256;
constexpr int HEADS = 8, HD = 32;
constexpr int NPIX = BATCH * HH * WW;   // 32768
constexpr int C3 = 3 * CH;              // 768
constexpr int NREL = 23 * 23;           // 529

// ---------------- device scratch (allocation-free) ----------------
__device__ float g_qkv[NPIX * C3];
__device__ float g_qn [NPIX * CH];
__device__ float g_kn [NPIX * CH];
__device__ float g_v  [NPIX * CH];
__device__ float g_att[NPIX * CH];
__device__ float g_btab[NREL * HEADS];

// ---------------- CPB relative-bias MLP ----------------
__device__ __forceinline__ float relcoord(int r) {
    float cs = (float)(r - 11) * (8.0f / 7.0f);
    float a = log1pf(fabsf(cs)) * (1.0f / 2.0794415416798357f);
    return cs > 0.0f ? a : (cs < 0.0f ? -a : 0.0f);
}

__global__ void cpb_kernel(const float* __restrict__ w1, const float* __restrict__ b1,
                           const float* __restrict__ w2, float* __restrict__ btab) {
    int i = blockIdx.x;
    float y0 = relcoord(i / 23), y1 = relcoord(i % 23);
    int t = threadIdx.x;
    float part[HEADS];
#pragma unroll
    for (int hh = 0; hh < HEADS; hh++) part[hh] = 0.0f;
    for (int j = t; j < 512; j += 256) {
        float hv = fmaf(y0, w1[j], fmaf(y1, w1[512 + j], b1[j]));
        hv = fmaxf(hv, 0.0f);
#pragma unroll
        for (int hh = 0; hh < HEADS; hh++) part[hh] = fmaf(hv, w2[j * HEADS + hh], part[hh]);
    }
#pragma unroll
    for (int hh = 0; hh < HEADS; hh++)
#pragma unroll
        for (int o = 16; o; o >>= 1) part[hh] += __shfl_xor_sync(0xffffffffu, part[hh], o);
    __shared__ float sm[HEADS][8];
    int lane = t & 31, wrp = t >> 5;
    if (lane == 0)
        for (int hh = 0; hh < HEADS; hh++) sm[hh][wrp] = part[hh];
    __syncthreads();
    if (t < HEADS) {
        float ssum = 0.0f;
        for (int k = 0; k < 8; k++) ssum += sm[t][k];
        btab[i * HEADS + t] = 16.0f / (1.0f + expf(-ssum));
    }
}

// ---------------- fp32 SGEMM (unchanged) ----------------
__global__ __launch_bounds__(256) void sgemm128(int M, int N, int K,
                                                const float* __restrict__ A,
                                                const float* __restrict__ B,
                                                float* __restrict__ C) {
    constexpr int BM = 128, BN = 128, BK = 8, TM = 8, TN = 8;
    __shared__ float As[BK][BM];
    __shared__ float Bs[BK][BN];
    int block_row = blockIdx.y, block_col = blockIdx.x;
    int tid = threadIdx.x;
    int tRow = tid / (BN / TN);
    int tCol = tid % (BN / TN);
    int aRow = tid >> 1;
    int aCol = (tid & 1) << 2;
    int bRow = tid >> 5;
    int bCol = (tid & 31) << 2;
    const float* Ab = A + (size_t)block_row * BM * K;
    const float* Bb = B + (size_t)block_col * BN;
    float acc[TM][TN];
#pragma unroll
    for (int i = 0; i < TM; i++)
#pragma unroll
        for (int j = 0; j < TN; j++) acc[i][j] = 0.0f;
    float ra[TM], rb[TN];
    for (int k0 = 0; k0 < K; k0 += BK) {
        float4 a4 = *(const float4*)(Ab + (size_t)aRow * K + k0 + aCol);
        As[aCol + 0][aRow] = a4.x; As[aCol + 1][aRow] = a4.y;
        As[aCol + 2][aRow] = a4.z; As[aCol + 3][aRow] = a4.w;
        float4 b4 = *(const float4*)(Bb + (size_t)(k0 + bRow) * N + bCol);
        *(float4*)(&Bs[bRow][bCol]) = b4;
        __syncthreads();
#pragma unroll
        for (int kk = 0; kk < BK; kk++) {
#pragma unroll
            for (int i = 0; i < TM; i++) ra[i] = As[kk][tRow * TM + i];
#pragma unroll
            for (int j = 0; j < TN; j++) rb[j] = Bs[kk][tCol * TN + j];
#pragma unroll
            for (int i = 0; i < TM; i++)
#pragma unroll
                for (int j = 0; j < TN; j++) acc[i][j] = fmaf(ra[i], rb[j], acc[i][j]);
        }
        __syncthreads();
    }
    float* Cb = C + (size_t)block_row * BM * N + block_col * BN;
#pragma unroll
    for (int i = 0; i < TM; i++) {
#pragma unroll
        for (int j = 0; j < TN; j += 4) {
            float4 v = {acc[i][j], acc[i][j + 1], acc[i][j + 2], acc[i][j + 3]};
            *(float4*)(Cb + (size_t)(tRow * TM + i) * N + tCol * TN + j) = v;
        }
    }
}

// ---------------- conv + LN + biases + l2norm (unchanged) ----------------
__global__ __launch_bounds__(768) void conv_ln_kernel(
    const float* __restrict__ qkv, const float* __restrict__ wdw,
    const float* __restrict__ ln_g, const float* __restrict__ ln_b,
    const float* __restrict__ q_bias, const float* __restrict__ v_bias,
    const float* __restrict__ logit_scale,
    float* __restrict__ qn, float* __restrict__ kn, float* __restrict__ vv) {
    int p = blockIdx.x;
    int b = p >> 14, y = (p >> 7) & 127, x = p & 127;
    int c = threadIdx.x;
    float acc = 0.0f;
#pragma unroll
    for (int dy = -1; dy <= 1; dy++) {
        int yy = y + dy;
        if ((unsigned)yy >= (unsigned)HH) continue;
#pragma unroll
        for (int dx = -1; dx <= 1; dx++) {
            int xx = x + dx;
            if ((unsigned)xx >= (unsigned)WW) continue;
            acc = fmaf(qkv[(size_t)(((b << 7) | yy) << 7 | xx) * C3 + c],
                       wdw[((dy + 1) * 3 + (dx + 1)) * C3 + c], acc);
        }
    }
    float s = acc, s2 = acc * acc;
#pragma unroll
    for (int o = 16; o; o >>= 1) {
        s  += __shfl_xor_sync(0xffffffffu, s, o);
        s2 += __shfl_xor_sync(0xffffffffu, s2, o);
    }
    __shared__ float ws[24], ws2[24];
    __shared__ float s_mu, s_rstd;
    int lane = c & 31, wrp = c >> 5;
    if (lane == 0) { ws[wrp] = s; ws2[wrp] = s2; }
    __syncthreads();
    if (c < 32) {
        float a  = (c < 24) ? ws[c]  : 0.0f;
        float a2 = (c < 24) ? ws2[c] : 0.0f;
#pragma unroll
        for (int o = 16; o; o >>= 1) {
            a  += __shfl_xor_sync(0xffffffffu, a, o);
            a2 += __shfl_xor_sync(0xffffffffu, a2, o);
        }
        if (c == 0) {
            float mu = a * (1.0f / 768.0f);
            float var = a2 * (1.0f / 768.0f) - mu * mu;
            s_mu = mu;
            s_rstd = rsqrtf(var + 1e-5f);
        }
    }
    __syncthreads();
    float val = (acc - s_mu) * s_rstd * ln_g[c] + ln_b[c];
    if (c < 256) {
        val += q_bias[c];
        float ss = val * val;
#pragma unroll
        for (int o = 16; o; o >>= 1) ss += __shfl_xor_sync(0xffffffffu, ss, o);
        float rn = rsqrtf(fmaxf(ss, 1.55e-5f));
        float sc = __expf(fminf(logit_scale[c >> 5], 4.6051701859880914f));
        qn[(size_t)p * CH + c] = val * rn * sc;
    } else if (c < 512) {
        float ss = val * val;
#pragma unroll
        for (int o = 16; o; o >>= 1) ss += __shfl_xor_sync(0xffffffffu, ss, o);
        kn[(size_t)p * CH + (c - 256)] = val * rsqrtf(fmaxf(ss, 1.55e-5f));
    } else {
        vv[(size_t)p * CH + (c - 512)] = val + v_bias[c - 512];
    }
}

// ---------------- attention: two-phase GEMM-tiled, bound-shifted softmax ----------------
// grid (512 windows, 8 heads), 256 threads. 2 chunks of 128 keys.
// Phase A: S = QK^T + bias -> p = exp(s - bound) into smem (8q x 4k tiles)
// Phase B: O += P V (8q x 4d tiles, 4-way key split)
// smem floats layout:
constexpr int SM_QS   = 0;                  // [32][64]
constexpr int SM_KS   = SM_QS + 32 * 64;    // [32][128]
constexpr int SM_VS   = SM_KS + 32 * 128;   // [128][36]
constexpr int SM_SP   = SM_VS + 128 * 36;   // [128][68]  (reused as Osm[4][64][33])
constexpr int SM_BSM  = SM_SP + 128 * 68;   // [529]
constexpr int SM_LRED = SM_BSM + NREL;      // [32][65]
constexpr int SM_LFIN = SM_LRED + 32 * 65;  // [64]
constexpr int SM_TOT  = SM_LFIN + 64;       // floats

__global__ __launch_bounds__(256, 2) void attn_kernel(
    const float* __restrict__ qn, const float* __restrict__ kn,
    const float* __restrict__ vv, const float* __restrict__ btab,
    const float* __restrict__ logit_scale, float* __restrict__ out) {
    extern __shared__ float sm[];
    float* Qs   = sm + SM_QS;
    float* Ks   = sm + SM_KS;
    float* Vs   = sm + SM_VS;
    float* Sp   = sm + SM_SP;
    float* bsm  = sm + SM_BSM;
    float* lred = sm + SM_LRED;
    float* lfin = sm + SM_LFIN;

    int w = blockIdx.x, h = blockIdx.y;
    int b = w >> 8, wr = (w >> 4) & 15, wc = w & 15;
    int t = threadIdx.x;
    float bound = __expf(fminf(logit_scale[h], 4.6051701859880914f)) + 16.0f;

    // bias table for this head
    for (int i = t; i < NREL; i += 256) bsm[i] = btab[i * HEADS + h];

    // load Q transposed: thread: query t&63, dims (t>>6)*8 .. +7
    {
        int qq = t & 63, d0 = (t >> 6) << 3;
        int qi = qq >> 3, qj = qq & 7;
        int py = wr * 8 + qi, px = wc * 8 + qj;
        const float* qp = qn + (size_t)(((b << 7) | py) << 7 | px) * CH + h * HD + d0;
        float4 a = *(const float4*)qp;
        float4 bq = *(const float4*)(qp + 4);
        Qs[(d0 + 0) * 64 + qq] = a.x;  Qs[(d0 + 1) * 64 + qq] = a.y;
        Qs[(d0 + 2) * 64 + qq] = a.z;  Qs[(d0 + 3) * 64 + qq] = a.w;
        Qs[(d0 + 4) * 64 + qq] = bq.x; Qs[(d0 + 5) * 64 + qq] = bq.y;
        Qs[(d0 + 6) * 64 + qq] = bq.z; Qs[(d0 + 7) * 64 + qq] = bq.w;
    }

    // A mapping: 8 queries (qg*4 + i, 32 + qg*4 + i), 4 keys (kgA*4 + j)
    int qgA = t & 7, kgA = t >> 3;
    // B mapping: 8 queries (qgB*4 + i, 32 + qgB*4 + i), 4 dims (dg*4), key-split ks
    int qgB = t & 7, dg = (t >> 3) & 7, ks = t >> 6;

    int qoff[8];
#pragma unroll
    for (int i = 0; i < 8; i++) {
        int qq = (i < 4) ? (qgA * 4 + i) : (32 + qgA * 4 + (i - 4));
        qoff[i] = (qq >> 3) * 23 + (qq & 7);
    }

    float O[8][4];
#pragma unroll
    for (int i = 0; i < 8; i++)
#pragma unroll
        for (int j = 0; j < 4; j++) O[i][j] = 0.0f;
    float lacc[8];
#pragma unroll
    for (int i = 0; i < 8; i++) lacc[i] = 0.0f;

    for (int c0 = 0; c0 < 2; c0++) {
        __syncthreads();   // previous B done reading Sp/Vs (also fences Qs/bsm on c0==0)
        // ---- load K,V chunk: key j = t&127, dims (t>>7)*16 .. +15 ----
        {
            int j = t & 127, d1 = (t >> 7) << 4;
            int jg = (c0 << 7) + j;
            int kr = jg >> 4, kc = jg & 15;
            int gy = wr * 8 - 4 + kr, gx = wc * 8 - 4 + kc;
            float4 k0 = {0,0,0,0}, k1 = {0,0,0,0}, k2 = {0,0,0,0}, k3 = {0,0,0,0};
            float4 v0 = {0,0,0,0}, v1 = {0,0,0,0}, v2 = {0,0,0,0}, v3 = {0,0,0,0};
            if ((unsigned)gy < 128u && (unsigned)gx < 128u) {
                size_t gb = (size_t)(((b << 7) | gy) << 7 | gx) * CH + h * HD + d1;
                k0 = *(const float4*)(kn + gb);      k1 = *(const float4*)(kn + gb + 4);
                k2 = *(const float4*)(kn + gb + 8);  k3 = *(const float4*)(kn + gb + 12);
                v0 = *(const float4*)(vv + gb);      v1 = *(const float4*)(vv + gb + 4);
                v2 = *(const float4*)(vv + gb + 8);  v3 = *(const float4*)(vv + gb + 12);
            }
            Ks[(d1 + 0) * 128 + j] = k0.x;  Ks[(d1 + 1) * 128 + j] = k0.y;
            Ks[(d1 + 2) * 128 + j] = k0.z;  Ks[(d1 + 3) * 128 + j] = k0.w;
            Ks[(d1 + 4) * 128 + j] = k1.x;  Ks[(d1 + 5) * 128 + j] = k1.y;
            Ks[(d1 + 6) * 128 + j] = k1.z;  Ks[(d1 + 7) * 128 + j] = k1.w;
            Ks[(d1 + 8) * 128 + j] = k2.x;  Ks[(d1 + 9) * 128 + j] = k2.y;
            Ks[(d1 +10) * 128 + j] = k2.z;  Ks[(d1 +11) * 128 + j] = k2.w;
            Ks[(d1 +12) * 128 + j] = k3.x;  Ks[(d1 +13) * 128 + j] = k3.y;
            Ks[(d1 +14) * 128 + j] = k3.z;  Ks[(d1 +15) * 128 + j] = k3.w;
            float* vp = &Vs[j * 36 + d1];
            *(float4*)(vp + 0) = v0; *(float4*)(vp + 4)  = v1;
            *(float4*)(vp + 8) = v2; *(float4*)(vp + 12) = v3;
        }
        __syncthreads();

        // ---- Phase A: S tile 8q x 4k ----
        float acc[8][4];
#pragma unroll
        for (int i = 0; i < 8; i++)
#pragma unroll
            for (int j = 0; j < 4; j++) acc[i][j] = 0.0f;
#pragma unroll 8
        for (int kk = 0; kk < 32; kk++) {
            float4 ra0 = *(const float4*)&Qs[kk * 64 + qgA * 4];
            float4 ra1 = *(const float4*)&Qs[kk * 64 + 32 + qgA * 4];
            float4 rb  = *(const float4*)&Ks[kk * 128 + kgA * 4];
            float a[8] = {ra0.x, ra0.y, ra0.z, ra0.w, ra1.x, ra1.y, ra1.z, ra1.w};
            float bk[4] = {rb.x, rb.y, rb.z, rb.w};
#pragma unroll
            for (int i = 0; i < 8; i++)
#pragma unroll
                for (int j = 0; j < 4; j++) acc[i][j] = fmaf(a[i], bk[j], acc[i][j]);
        }
        // bias + exp + store P
#pragma unroll
        for (int j = 0; j < 4; j++) {
            int krow = kgA * 4 + j;
            int jg = (c0 << 7) + krow;
            int base = (15 - (jg >> 4)) * 23 + (15 - (jg & 15));
            float p[8];
#pragma unroll
            for (int i = 0; i < 8; i++) {
                p[i] = __expf(acc[i][j] - bound + bsm[base + qoff[i]]);
                lacc[i] += p[i];
            }
            float4 p03 = {p[0], p[1], p[2], p[3]};
            float4 p47 = {p[4], p[5], p[6], p[7]};
            *(float4*)&Sp[krow * 68 + qgA * 4]      = p03;
            *(float4*)&Sp[krow * 68 + 32 + qgA * 4] = p47;
        }
        __syncthreads();

        // ---- Phase B: O += P V, 8q x 4d, keys ks*32 .. +31 ----
#pragma unroll 4
        for (int jj = 0; jj < 32; jj++) {
            int jr = ks * 32 + jj;
            float4 p0 = *(const float4*)&Sp[jr * 68 + qgB * 4];
            float4 p1 = *(const float4*)&Sp[jr * 68 + 32 + qgB * 4];
            float4 v4 = *(const float4*)&Vs[jr * 36 + dg * 4];
            float p[8] = {p0.x, p0.y, p0.z, p0.w, p1.x, p1.y, p1.z, p1.w};
            float vr[4] = {v4.x, v4.y, v4.z, v4.w};
#pragma unroll
            for (int i = 0; i < 8; i++)
#pragma unroll
                for (int d = 0; d < 4; d++) O[i][d] = fmaf(p[i], vr[d], O[i][d]);
        }
    }
    __syncthreads();

    // ---- reductions ----
#pragma unroll
    for (int i = 0; i < 8; i++) {
        int qq = (i < 4) ? (qgA * 4 + i) : (32 + qgA * 4 + (i - 4));
        lred[kgA * 65 + qq] = lacc[i];
    }
    float* Osm = Sp;  // [4][64][33]
#pragma unroll
    for (int i = 0; i < 8; i++) {
        int qq = (i < 4) ? (qgB * 4 + i) : (32 + qgB * 4 + (i - 4));
#pragma unroll
        for (int d = 0; d < 4; d++)
            Osm[(ks * 64 + qq) * 33 + dg * 4 + d] = O[i][d];
    }
    __syncthreads();
    if (t < 64) {
        float ssum = 0.0f;
#pragma unroll
        for (int g = 0; g < 32; g++) ssum += lred[g * 65 + t];
        lfin[t] = 1.0f / ssum;
    }
    __syncthreads();

    // final combine + write: thread: query t>>2, dims (t&3)*8 .. +7
    {
        int qq = t >> 2, d0 = (t & 3) << 3;
        float inv = lfin[qq];
        float o[8];
#pragma unroll
        for (int d = 0; d < 8; d++) {
            o[d] = (Osm[(qq) * 33 + d0 + d] + Osm[(64 + qq) * 33 + d0 + d] +
                    Osm[(128 + qq) * 33 + d0 + d] + Osm[(192 + qq) * 33 + d0 + d]) * inv;
        }
        int qi = qq >> 3, qj = qq & 7;
        int py = wr * 8 + qi, px = wc * 8 + qj;
        float* op = out + (size_t)(((b << 7) | py) << 7 | px) * CH + h * HD + d0;
        float4 o0 = {o[0], o[1], o[2], o[3]};
        float4 o1 = {o[4], o[5], o[6], o[7]};
        *(float4*)op = o0;
        *(float4*)(op + 4) = o1;
    }
}

// ---------------- launch ----------------
extern "C" void kernel_launch(void* const* d_in, const int* in_sizes, int n_in,
                              void* d_out, int out_size) {
    const float* x           = (const float*)d_in[0];
    const float* w_qkv       = (const float*)d_in[1];
    const float* w_dw        = (const float*)d_in[2];
    const float* ln_g        = (const float*)d_in[3];
    const float* ln_b        = (const float*)d_in[4];
    const float* q_bias      = (const float*)d_in[5];
    const float* v_bias      = (const float*)d_in[6];
    const float* logit_scale = (const float*)d_in[7];
    const float* cpb_w1      = (const float*)d_in[8];
    const float* cpb_b1      = (const float*)d_in[9];
    const float* cpb_w2      = (const float*)d_in[10];
    const float* w_proj      = (const float*)d_in[11];
    float* out = (float*)d_out;

    float *qkv, *qn, *kn, *vv, *att, *btab;
    cudaGetSymbolAddress((void**)&qkv,  g_qkv);
    cudaGetSymbolAddress((void**)&qn,   g_qn);
    cudaGetSymbolAddress((void**)&kn,   g_kn);
    cudaGetSymbolAddress((void**)&vv,   g_v);
    cudaGetSymbolAddress((void**)&att,  g_att);
    cudaGetSymbolAddress((void**)&btab, g_btab);

    int smem_bytes = SM_TOT * 4;
    cudaFuncSetAttribute(attn_kernel, cudaFuncAttributeMaxDynamicSharedMemorySize, smem_bytes);

    cpb_kernel<<<NREL, 256>>>(cpb_w1, cpb_b1, cpb_w2, btab);
    sgemm128<<<dim3(C3 / 128, NPIX / 128), 256>>>(NPIX, C3, CH, x, w_qkv, qkv);
    conv_ln_kernel<<<NPIX, 768>>>(qkv, w_dw, ln_g, ln_b, q_bias, v_bias, logit_scale,
                                  qn, kn, vv);
    attn_kernel<<<dim3(512, 8), 256, smem_bytes>>>(qn, kn, vv, btab, logit_scale, att);
    sgemm128<<<dim3(CH / 128, NPIX / 128), 256>>>(NPIX, CH, CH, att, w_proj, out);
}

// round 3
// speedup vs baseline: 1.7473x; 1.3565x over previous
#include <cuda_runtime.h>
#include <math.h>

// ---------------- problem constants ----------------
constexpr int BATCH = 2, HH = 128, WW = 128, CH = 256;
constexpr int HEADS = 8, HD = 32;
constexpr int NPIX = BATCH * HH * WW;   // 32768
constexpr int C3 = 3 * CH;              // 768
constexpr int NREL = 23 * 23;           // 529

// ---------------- device scratch (allocation-free) ----------------
__device__ float g_qkv[NPIX * C3];
__device__ float g_qn [NPIX * CH];
__device__ float g_kn [NPIX * CH];
__device__ float g_v  [NPIX * CH];
__device__ float g_att[NPIX * CH];
__device__ float g_btab[NREL * HEADS];

// ---------------- CPB relative-bias MLP ----------------
__device__ __forceinline__ float relcoord(int r) {
    float cs = (float)(r - 11) * (8.0f / 7.0f);
    float a = log1pf(fabsf(cs)) * (1.0f / 2.0794415416798357f);
    return cs > 0.0f ? a : (cs < 0.0f ? -a : 0.0f);
}

__global__ void cpb_kernel(const float* __restrict__ w1, const float* __restrict__ b1,
                           const float* __restrict__ w2, float* __restrict__ btab) {
    int i = blockIdx.x;
    float y0 = relcoord(i / 23), y1 = relcoord(i % 23);
    int t = threadIdx.x;
    float part[HEADS];
#pragma unroll
    for (int hh = 0; hh < HEADS; hh++) part[hh] = 0.0f;
    for (int j = t; j < 512; j += 256) {
        float hv = fmaf(y0, w1[j], fmaf(y1, w1[512 + j], b1[j]));
        hv = fmaxf(hv, 0.0f);
#pragma unroll
        for (int hh = 0; hh < HEADS; hh++) part[hh] = fmaf(hv, w2[j * HEADS + hh], part[hh]);
    }
#pragma unroll
    for (int hh = 0; hh < HEADS; hh++)
#pragma unroll
        for (int o = 16; o; o >>= 1) part[hh] += __shfl_xor_sync(0xffffffffu, part[hh], o);
    __shared__ float sm[HEADS][8];
    int lane = t & 31, wrp = t >> 5;
    if (lane == 0)
        for (int hh = 0; hh < HEADS; hh++) sm[hh][wrp] = part[hh];
    __syncthreads();
    if (t < HEADS) {
        float ssum = 0.0f;
        for (int k = 0; k < 8; k++) ssum += sm[t][k];
        btab[i * HEADS + t] = 16.0f / (1.0f + expf(-ssum));
    }
}

// ---------------- tf32 tensor-core GEMM: C[M,N] = A[M,K] @ B[K,N], row-major ----------------
// BM=BN=128, BK=32, 256 threads = 8 warps (2 x 4), warp tile 64x32,
// mma.sync.aligned.m16n8k8.row.col.f32.tf32.tf32.f32
__device__ __forceinline__ unsigned f2tf32(float x) {
    unsigned r;
    asm("cvt.rna.tf32.f32 %0, %1;" : "=r"(r) : "f"(x));
    return r;
}

__global__ __launch_bounds__(256) void mma_gemm(int M, int N, int K,
                                                const float* __restrict__ A,
                                                const float* __restrict__ B,
                                                float* __restrict__ C) {
    constexpr int BM = 128, BN = 128, BK = 32;
    constexpr int AST = BK + 4;    // 36: A frag bank = 4*(lane>>2)+(lane&3) -> conflict-free
    constexpr int BST = BN + 8;    // 136: B frag bank = 8*(lane&3)+(lane>>2) -> conflict-free
    __shared__ unsigned As[BM * AST];
    __shared__ unsigned Bs[BK * BST];
    int tid = threadIdx.x;
    int warp = tid >> 5, lane = tid & 31;
    int wm = (warp & 1) * 64, wn = (warp >> 1) * 32;
    int brow = blockIdx.y * BM, bcol = blockIdx.x * BN;
    int grp = lane >> 2, thr = lane & 3;

    float acc[4][4][4];
#pragma unroll
    for (int i = 0; i < 4; i++)
#pragma unroll
        for (int j = 0; j < 4; j++)
#pragma unroll
            for (int r = 0; r < 4; r++) acc[i][j][r] = 0.0f;

    int aRow = tid >> 1, aCol = (tid & 1) << 4;     // A: row 0..127, col 0 or 16
    int bRow = tid >> 3, bCol = (tid & 7) << 4;     // B: row 0..31,  col 0..112

    const float* Ap = A + (size_t)(brow + aRow) * K + aCol;
    const float* Bp = B + (size_t)bRow * N + bcol + bCol;

    for (int k0 = 0; k0 < K; k0 += BK) {
        // stage A (tf32-rounded)
#pragma unroll
        for (int i = 0; i < 4; i++) {
            float4 v = *(const float4*)(Ap + k0 + i * 4);
            unsigned* dst = &As[aRow * AST + aCol + i * 4];
            dst[0] = f2tf32(v.x); dst[1] = f2tf32(v.y);
            dst[2] = f2tf32(v.z); dst[3] = f2tf32(v.w);
        }
        // stage B
#pragma unroll
        for (int i = 0; i < 4; i++) {
            float4 v = *(const float4*)(Bp + (size_t)k0 * N + i * 4);
            unsigned* dst = &Bs[bRow * BST + bCol + i * 4];
            dst[0] = f2tf32(v.x); dst[1] = f2tf32(v.y);
            dst[2] = f2tf32(v.z); dst[3] = f2tf32(v.w);
        }
        __syncthreads();

#pragma unroll
        for (int kstep = 0; kstep < 4; kstep++) {
            int kb = kstep * 8;
            unsigned a[4][4], b[4][2];
#pragma unroll
            for (int mt = 0; mt < 4; mt++) {
                int r0 = wm + mt * 16 + grp;
                int ca = kb + thr;
                a[mt][0] = As[r0 * AST + ca];
                a[mt][1] = As[(r0 + 8) * AST + ca];
                a[mt][2] = As[r0 * AST + ca + 4];
                a[mt][3] = As[(r0 + 8) * AST + ca + 4];
            }
#pragma unroll
            for (int nt = 0; nt < 4; nt++) {
                int kr = kb + thr;
                int nc = wn + nt * 8 + grp;
                b[nt][0] = Bs[kr * BST + nc];
                b[nt][1] = Bs[(kr + 4) * BST + nc];
            }
#pragma unroll
            for (int mt = 0; mt < 4; mt++)
#pragma unroll
                for (int nt = 0; nt < 4; nt++) {
                    asm volatile(
                        "mma.sync.aligned.m16n8k8.row.col.f32.tf32.tf32.f32 "
                        "{%0,%1,%2,%3}, {%4,%5,%6,%7}, {%8,%9}, {%0,%1,%2,%3};"
                        : "+f"(acc[mt][nt][0]), "+f"(acc[mt][nt][1]),
                          "+f"(acc[mt][nt][2]), "+f"(acc[mt][nt][3])
                        : "r"(a[mt][0]), "r"(a[mt][1]), "r"(a[mt][2]), "r"(a[mt][3]),
                          "r"(b[nt][0]), "r"(b[nt][1]));
                }
        }
        __syncthreads();
    }

    // epilogue: c0=C[grp][2thr], c1=+1, c2=C[grp+8][2thr], c3=+1
#pragma unroll
    for (int mt = 0; mt < 4; mt++) {
#pragma unroll
        for (int nt = 0; nt < 4; nt++) {
            int row = brow + wm + mt * 16 + grp;
            int col = bcol + wn + nt * 8 + thr * 2;
            float2 v0 = {acc[mt][nt][0], acc[mt][nt][1]};
            float2 v1 = {acc[mt][nt][2], acc[mt][nt][3]};
            *(float2*)(C + (size_t)row * N + col) = v0;
            *(float2*)(C + (size_t)(row + 8) * N + col) = v1;
        }
    }
}

// ---------------- conv + LN + biases + l2norm (unchanged) ----------------
__global__ __launch_bounds__(768) void conv_ln_kernel(
    const float* __restrict__ qkv, const float* __restrict__ wdw,
    const float* __restrict__ ln_g, const float* __restrict__ ln_b,
    const float* __restrict__ q_bias, const float* __restrict__ v_bias,
    const float* __restrict__ logit_scale,
    float* __restrict__ qn, float* __restrict__ kn, float* __restrict__ vv) {
    int p = blockIdx.x;
    int b = p >> 14, y = (p >> 7) & 127, x = p & 127;
    int c = threadIdx.x;
    float acc = 0.0f;
#pragma unroll
    for (int dy = -1; dy <= 1; dy++) {
        int yy = y + dy;
        if ((unsigned)yy >= (unsigned)HH) continue;
#pragma unroll
        for (int dx = -1; dx <= 1; dx++) {
            int xx = x + dx;
            if ((unsigned)xx >= (unsigned)WW) continue;
            acc = fmaf(qkv[(size_t)(((b << 7) | yy) << 7 | xx) * C3 + c],
                       wdw[((dy + 1) * 3 + (dx + 1)) * C3 + c], acc);
        }
    }
    float s = acc, s2 = acc * acc;
#pragma unroll
    for (int o = 16; o; o >>= 1) {
        s  += __shfl_xor_sync(0xffffffffu, s, o);
        s2 += __shfl_xor_sync(0xffffffffu, s2, o);
    }
    __shared__ float ws[24], ws2[24];
    __shared__ float s_mu, s_rstd;
    int lane = c & 31, wrp = c >> 5;
    if (lane == 0) { ws[wrp] = s; ws2[wrp] = s2; }
    __syncthreads();
    if (c < 32) {
        float a  = (c < 24) ? ws[c]  : 0.0f;
        float a2 = (c < 24) ? ws2[c] : 0.0f;
#pragma unroll
        for (int o = 16; o; o >>= 1) {
            a  += __shfl_xor_sync(0xffffffffu, a, o);
            a2 += __shfl_xor_sync(0xffffffffu, a2, o);
        }
        if (c == 0) {
            float mu = a * (1.0f / 768.0f);
            float var = a2 * (1.0f / 768.0f) - mu * mu;
            s_mu = mu;
            s_rstd = rsqrtf(var + 1e-5f);
        }
    }
    __syncthreads();
    float val = (acc - s_mu) * s_rstd * ln_g[c] + ln_b[c];
    if (c < 256) {
        val += q_bias[c];
        float ss = val * val;
#pragma unroll
        for (int o = 16; o; o >>= 1) ss += __shfl_xor_sync(0xffffffffu, ss, o);
        float rn = rsqrtf(fmaxf(ss, 1.55e-5f));
        float sc = __expf(fminf(logit_scale[c >> 5], 4.6051701859880914f));
        qn[(size_t)p * CH + c] = val * rn * sc;
    } else if (c < 512) {
        float ss = val * val;
#pragma unroll
        for (int o = 16; o; o >>= 1) ss += __shfl_xor_sync(0xffffffffu, ss, o);
        kn[(size_t)p * CH + (c - 256)] = val * rsqrtf(fmaxf(ss, 1.55e-5f));
    } else {
        vv[(size_t)p * CH + (c - 512)] = val + v_bias[c - 512];
    }
}

// ---------------- attention (unchanged from R2) ----------------
constexpr int SM_QS   = 0;
constexpr int SM_KS   = SM_QS + 32 * 64;
constexpr int SM_VS   = SM_KS + 32 * 128;
constexpr int SM_SP   = SM_VS + 128 * 36;
constexpr int SM_BSM  = SM_SP + 128 * 68;
constexpr int SM_LRED = SM_BSM + NREL;
constexpr int SM_LFIN = SM_LRED + 32 * 65;
constexpr int SM_TOT  = SM_LFIN + 64;

__global__ __launch_bounds__(256, 2) void attn_kernel(
    const float* __restrict__ qn, const float* __restrict__ kn,
    const float* __restrict__ vv, const float* __restrict__ btab,
    const float* __restrict__ logit_scale, float* __restrict__ out) {
    extern __shared__ float sm[];
    float* Qs   = sm + SM_QS;
    float* Ks   = sm + SM_KS;
    float* Vs   = sm + SM_VS;
    float* Sp   = sm + SM_SP;
    float* bsm  = sm + SM_BSM;
    float* lred = sm + SM_LRED;
    float* lfin = sm + SM_LFIN;

    int w = blockIdx.x, h = blockIdx.y;
    int b = w >> 8, wr = (w >> 4) & 15, wc = w & 15;
    int t = threadIdx.x;
    float bound = __expf(fminf(logit_scale[h], 4.6051701859880914f)) + 16.0f;

    for (int i = t; i < NREL; i += 256) bsm[i] = btab[i * HEADS + h];

    {
        int qq = t & 63, d0 = (t >> 6) << 3;
        int qi = qq >> 3, qj = qq & 7;
        int py = wr * 8 + qi, px = wc * 8 + qj;
        const float* qp = qn + (size_t)(((b << 7) | py) << 7 | px) * CH + h * HD + d0;
        float4 a = *(const float4*)qp;
        float4 bq = *(const float4*)(qp + 4);
        Qs[(d0 + 0) * 64 + qq] = a.x;  Qs[(d0 + 1) * 64 + qq] = a.y;
        Qs[(d0 + 2) * 64 + qq] = a.z;  Qs[(d0 + 3) * 64 + qq] = a.w;
        Qs[(d0 + 4) * 64 + qq] = bq.x; Qs[(d0 + 5) * 64 + qq] = bq.y;
        Qs[(d0 + 6) * 64 + qq] = bq.z; Qs[(d0 + 7) * 64 + qq] = bq.w;
    }

    int qgA = t & 7, kgA = t >> 3;
    int qgB = t & 7, dg = (t >> 3) & 7, ks = t >> 6;

    int qoff[8];
#pragma unroll
    for (int i = 0; i < 8; i++) {
        int qq = (i < 4) ? (qgA * 4 + i) : (32 + qgA * 4 + (i - 4));
        qoff[i] = (qq >> 3) * 23 + (qq & 7);
    }

    float O[8][4];
#pragma unroll
    for (int i = 0; i < 8; i++)
#pragma unroll
        for (int j = 0; j < 4; j++) O[i][j] = 0.0f;
    float lacc[8];
#pragma unroll
    for (int i = 0; i < 8; i++) lacc[i] = 0.0f;

    for (int c0 = 0; c0 < 2; c0++) {
        __syncthreads();
        {
            int j = t & 127, d1 = (t >> 7) << 4;
            int jg = (c0 << 7) + j;
            int kr = jg >> 4, kc = jg & 15;
            int gy = wr * 8 - 4 + kr, gx = wc * 8 - 4 + kc;
            float4 k0 = {0,0,0,0}, k1 = {0,0,0,0}, k2 = {0,0,0,0}, k3 = {0,0,0,0};
            float4 v0 = {0,0,0,0}, v1 = {0,0,0,0}, v2 = {0,0,0,0}, v3 = {0,0,0,0};
            if ((unsigned)gy < 128u && (unsigned)gx < 128u) {
                size_t gb = (size_t)(((b << 7) | gy) << 7 | gx) * CH + h * HD + d1;
                k0 = *(const float4*)(kn + gb);      k1 = *(const float4*)(kn + gb + 4);
                k2 = *(const float4*)(kn + gb + 8);  k3 = *(const float4*)(kn + gb + 12);
                v0 = *(const float4*)(vv + gb);      v1 = *(const float4*)(vv + gb + 4);
                v2 = *(const float4*)(vv + gb + 8);  v3 = *(const float4*)(vv + gb + 12);
            }
            Ks[(d1 + 0) * 128 + j] = k0.x;  Ks[(d1 + 1) * 128 + j] = k0.y;
            Ks[(d1 + 2) * 128 + j] = k0.z;  Ks[(d1 + 3) * 128 + j] = k0.w;
            Ks[(d1 + 4) * 128 + j] = k1.x;  Ks[(d1 + 5) * 128 + j] = k1.y;
            Ks[(d1 + 6) * 128 + j] = k1.z;  Ks[(d1 + 7) * 128 + j] = k1.w;
            Ks[(d1 + 8) * 128 + j] = k2.x;  Ks[(d1 + 9) * 128 + j] = k2.y;
            Ks[(d1 +10) * 128 + j] = k2.z;  Ks[(d1 +11) * 128 + j] = k2.w;
            Ks[(d1 +12) * 128 + j] = k3.x;  Ks[(d1 +13) * 128 + j] = k3.y;
            Ks[(d1 +14) * 128 + j] = k3.z;  Ks[(d1 +15) * 128 + j] = k3.w;
            float* vp = &Vs[j * 36 + d1];
            *(float4*)(vp + 0) = v0; *(float4*)(vp + 4)  = v1;
            *(float4*)(vp + 8) = v2; *(float4*)(vp + 12) = v3;
        }
        __syncthreads();

        float acc[8][4];
#pragma unroll
        for (int i = 0; i < 8; i++)
#pragma unroll
            for (int j = 0; j < 4; j++) acc[i][j] = 0.0f;
#pragma unroll 8
        for (int kk = 0; kk < 32; kk++) {
            float4 ra0 = *(const float4*)&Qs[kk * 64 + qgA * 4];
            float4 ra1 = *(const float4*)&Qs[kk * 64 + 32 + qgA * 4];
            float4 rb  = *(const float4*)&Ks[kk * 128 + kgA * 4];
            float a[8] = {ra0.x, ra0.y, ra0.z, ra0.w, ra1.x, ra1.y, ra1.z, ra1.w};
            float bk[4] = {rb.x, rb.y, rb.z, rb.w};
#pragma unroll
            for (int i = 0; i < 8; i++)
#pragma unroll
                for (int j = 0; j < 4; j++) acc[i][j] = fmaf(a[i], bk[j], acc[i][j]);
        }
#pragma unroll
        for (int j = 0; j < 4; j++) {
            int krow = kgA * 4 + j;
            int jg = (c0 << 7) + krow;
            int base = (15 - (jg >> 4)) * 23 + (15 - (jg & 15));
            float p[8];
#pragma unroll
            for (int i = 0; i < 8; i++) {
                p[i] = __expf(acc[i][j] - bound + bsm[base + qoff[i]]);
                lacc[i] += p[i];
            }
            float4 p03 = {p[0], p[1], p[2], p[3]};
            float4 p47 = {p[4], p[5], p[6], p[7]};
            *(float4*)&Sp[krow * 68 + qgA * 4]      = p03;
            *(float4*)&Sp[krow * 68 + 32 + qgA * 4] = p47;
        }
        __syncthreads();

#pragma unroll 4
        for (int jj = 0; jj < 32; jj++) {
            int jr = ks * 32 + jj;
            float4 p0 = *(const float4*)&Sp[jr * 68 + qgB * 4];
            float4 p1 = *(const float4*)&Sp[jr * 68 + 32 + qgB * 4];
            float4 v4 = *(const float4*)&Vs[jr * 36 + dg * 4];
            float p[8] = {p0.x, p0.y, p0.z, p0.w, p1.x, p1.y, p1.z, p1.w};
            float vr[4] = {v4.x, v4.y, v4.z, v4.w};
#pragma unroll
            for (int i = 0; i < 8; i++)
#pragma unroll
                for (int d = 0; d < 4; d++) O[i][d] = fmaf(p[i], vr[d], O[i][d]);
        }
    }
    __syncthreads();

#pragma unroll
    for (int i = 0; i < 8; i++) {
        int qq = (i < 4) ? (qgA * 4 + i) : (32 + qgA * 4 + (i - 4));
        lred[kgA * 65 + qq] = lacc[i];
    }
    float* Osm = Sp;
#pragma unroll
    for (int i = 0; i < 8; i++) {
        int qq = (i < 4) ? (qgB * 4 + i) : (32 + qgB * 4 + (i - 4));
#pragma unroll
        for (int d = 0; d < 4; d++)
            Osm[(ks * 64 + qq) * 33 + dg * 4 + d] = O[i][d];
    }
    __syncthreads();
    if (t < 64) {
        float ssum = 0.0f;
#pragma unroll
        for (int g = 0; g < 32; g++) ssum += lred[g * 65 + t];
        lfin[t] = 1.0f / ssum;
    }
    __syncthreads();

    {
        int qq = t >> 2, d0 = (t & 3) << 3;
        float inv = lfin[qq];
        float o[8];
#pragma unroll
        for (int d = 0; d < 8; d++) {
            o[d] = (Osm[(qq) * 33 + d0 + d] + Osm[(64 + qq) * 33 + d0 + d] +
                    Osm[(128 + qq) * 33 + d0 + d] + Osm[(192 + qq) * 33 + d0 + d]) * inv;
        }
        int qi = qq >> 3, qj = qq & 7;
        int py = wr * 8 + qi, px = wc * 8 + qj;
        float* op = out + (size_t)(((b << 7) | py) << 7 | px) * CH + h * HD + d0;
        float4 o0 = {o[0], o[1], o[2], o[3]};
        float4 o1 = {o[4], o[5], o[6], o[7]};
        *(float4*)op = o0;
        *(float4*)(op + 4) = o1;
    }
}

// ---------------- launch ----------------
extern "C" void kernel_launch(void* const* d_in, const int* in_sizes, int n_in,
                              void* d_out, int out_size) {
    const float* x           = (const float*)d_in[0];
    const float* w_qkv       = (const float*)d_in[1];
    const float* w_dw        = (const float*)d_in[2];
    const float* ln_g        = (const float*)d_in[3];
    const float* ln_b        = (const float*)d_in[4];
    const float* q_bias      = (const float*)d_in[5];
    const float* v_bias      = (const float*)d_in[6];
    const float* logit_scale = (const float*)d_in[7];
    const float* cpb_w1      = (const float*)d_in[8];
    const float* cpb_b1      = (const float*)d_in[9];
    const float* cpb_w2      = (const float*)d_in[10];
    const float* w_proj      = (const float*)d_in[11];
    float* out = (float*)d_out;

    float *qkv, *qn, *kn, *vv, *att, *btab;
    cudaGetSymbolAddress((void**)&qkv,  g_qkv);
    cudaGetSymbolAddress((void**)&qn,   g_qn);
    cudaGetSymbolAddress((void**)&kn,   g_kn);
    cudaGetSymbolAddress((void**)&vv,   g_v);
    cudaGetSymbolAddress((void**)&att,  g_att);
    cudaGetSymbolAddress((void**)&btab, g_btab);

    int smem_bytes = SM_TOT * 4;
    cudaFuncSetAttribute(attn_kernel, cudaFuncAttributeMaxDynamicSharedMemorySize, smem_bytes);

    cpb_kernel<<<NREL, 256>>>(cpb_w1, cpb_b1, cpb_w2, btab);
    mma_gemm<<<dim3(C3 / 128, NPIX / 128), 256>>>(NPIX, C3, CH, x, w_qkv, qkv);
    conv_ln_kernel<<<NPIX, 768>>>(qkv, w_dw, ln_g, ln_b, q_bias, v_bias, logit_scale,
                                  qn, kn, vv);
    attn_kernel<<<dim3(512, 8), 256, smem_bytes>>>(qn, kn, vv, btab, logit_scale, att);
    mma_gemm<<<dim3(CH / 128, NPIX / 128), 256>>>(NPIX, CH, CH, att, w_proj, out);
}

// round 4
// speedup vs baseline: 2.0128x; 1.1519x over previous
#include <cuda_runtime.h>
#include <math.h>

// ---------------- problem constants ----------------
constexpr int BATCH = 2, HH = 128, WW = 128, CH = 256;
constexpr int HEADS = 8, HD = 32;
constexpr int NPIX = BATCH * HH * WW;   // 32768
constexpr int C3 = 3 * CH;              // 768
constexpr int NREL = 23 * 23;           // 529

// ---------------- device scratch (allocation-free) ----------------
__device__ float g_qkv[NPIX * C3];
__device__ float g_qn [NPIX * CH];
__device__ float g_kn [NPIX * CH];
__device__ float g_v  [NPIX * CH];
__device__ float g_att[NPIX * CH];
__device__ float g_btab[NREL * HEADS];

// ---------------- CPB relative-bias MLP ----------------
__device__ __forceinline__ float relcoord(int r) {
    float cs = (float)(r - 11) * (8.0f / 7.0f);
    float a = log1pf(fabsf(cs)) * (1.0f / 2.0794415416798357f);
    return cs > 0.0f ? a : (cs < 0.0f ? -a : 0.0f);
}

__global__ void cpb_kernel(const float* __restrict__ w1, const float* __restrict__ b1,
                           const float* __restrict__ w2, float* __restrict__ btab) {
    int i = blockIdx.x;
    float y0 = relcoord(i / 23), y1 = relcoord(i % 23);
    int t = threadIdx.x;
    float part[HEADS];
#pragma unroll
    for (int hh = 0; hh < HEADS; hh++) part[hh] = 0.0f;
    for (int j = t; j < 512; j += 256) {
        float hv = fmaf(y0, w1[j], fmaf(y1, w1[512 + j], b1[j]));
        hv = fmaxf(hv, 0.0f);
#pragma unroll
        for (int hh = 0; hh < HEADS; hh++) part[hh] = fmaf(hv, w2[j * HEADS + hh], part[hh]);
    }
#pragma unroll
    for (int hh = 0; hh < HEADS; hh++)
#pragma unroll
        for (int o = 16; o; o >>= 1) part[hh] += __shfl_xor_sync(0xffffffffu, part[hh], o);
    __shared__ float sm[HEADS][8];
    int lane = t & 31, wrp = t >> 5;
    if (lane == 0)
        for (int hh = 0; hh < HEADS; hh++) sm[hh][wrp] = part[hh];
    __syncthreads();
    if (t < HEADS) {
        float ssum = 0.0f;
        for (int k = 0; k < 8; k++) ssum += sm[t][k];
        btab[i * HEADS + t] = 16.0f / (1.0f + expf(-ssum));
    }
}

// ---------------- tf32 tensor-core GEMM, double-buffered ----------------
__device__ __forceinline__ unsigned f2tf32(float x) {
    unsigned r;
    asm("cvt.rna.tf32.f32 %0, %1;" : "=r"(r) : "f"(x));
    return r;
}

constexpr int GBM = 128, GBN = 128, GBK = 32;
constexpr int AST = GBK + 4;   // 36
constexpr int BST = GBN + 8;   // 136
constexpr int ABUF = GBM * AST;   // 4608 words
constexpr int BBUF = GBK * BST;   // 4352 words
constexpr int GEMM_SMEM = 2 * (ABUF + BBUF) * 4;  // 71680 bytes

__global__ __launch_bounds__(256) void mma_gemm(int M, int N, int K,
                                                const float* __restrict__ A,
                                                const float* __restrict__ B,
                                                float* __restrict__ C) {
    extern __shared__ unsigned smu[];
    unsigned* Asb[2] = {smu, smu + ABUF};
    unsigned* Bsb[2] = {smu + 2 * ABUF, smu + 2 * ABUF + BBUF};

    int tid = threadIdx.x;
    int warp = tid >> 5, lane = tid & 31;
    int wm = (warp & 1) * 64, wn = (warp >> 1) * 32;
    int brow = blockIdx.y * GBM, bcol = blockIdx.x * GBN;
    int grp = lane >> 2, thr = lane & 3;

    float acc[4][4][4];
#pragma unroll
    for (int i = 0; i < 4; i++)
#pragma unroll
        for (int j = 0; j < 4; j++)
#pragma unroll
            for (int r = 0; r < 4; r++) acc[i][j][r] = 0.0f;

    int aRow = tid >> 1, aCol = (tid & 1) << 4;
    int bRow = tid >> 3, bCol = (tid & 7) << 4;

    const float* Ap = A + (size_t)(brow + aRow) * K + aCol;
    const float* Bp = B + (size_t)bRow * N + bcol + bCol;

    float4 ra[4], rb[4];
    int niter = K / GBK;

    // prologue: load tile 0 and stage into buffer 0
#pragma unroll
    for (int i = 0; i < 4; i++) ra[i] = *(const float4*)(Ap + i * 4);
#pragma unroll
    for (int i = 0; i < 4; i++) rb[i] = *(const float4*)(Bp + i * 4);
#pragma unroll
    for (int i = 0; i < 4; i++) {
        unsigned* d = &Asb[0][aRow * AST + aCol + i * 4];
        d[0] = f2tf32(ra[i].x); d[1] = f2tf32(ra[i].y);
        d[2] = f2tf32(ra[i].z); d[3] = f2tf32(ra[i].w);
        unsigned* e = &Bsb[0][bRow * BST + bCol + i * 4];
        e[0] = f2tf32(rb[i].x); e[1] = f2tf32(rb[i].y);
        e[2] = f2tf32(rb[i].z); e[3] = f2tf32(rb[i].w);
    }
    __syncthreads();

    for (int iter = 0; iter < niter; iter++) {
        int nxt = iter + 1;
        if (nxt < niter) {
#pragma unroll
            for (int i = 0; i < 4; i++) ra[i] = *(const float4*)(Ap + nxt * GBK + i * 4);
#pragma unroll
            for (int i = 0; i < 4; i++) rb[i] = *(const float4*)(Bp + (size_t)nxt * GBK * N + i * 4);
        }
        const unsigned* Acur = Asb[iter & 1];
        const unsigned* Bcur = Bsb[iter & 1];
#pragma unroll
        for (int kstep = 0; kstep < 4; kstep++) {
            int kb = kstep * 8;
            unsigned a[4][4], bfr[4][2];
#pragma unroll
            for (int mt = 0; mt < 4; mt++) {
                int r0 = wm + mt * 16 + grp;
                int ca = kb + thr;
                a[mt][0] = Acur[r0 * AST + ca];
                a[mt][1] = Acur[(r0 + 8) * AST + ca];
                a[mt][2] = Acur[r0 * AST + ca + 4];
                a[mt][3] = Acur[(r0 + 8) * AST + ca + 4];
            }
#pragma unroll
            for (int nt = 0; nt < 4; nt++) {
                int kr = kb + thr;
                int nc = wn + nt * 8 + grp;
                bfr[nt][0] = Bcur[kr * BST + nc];
                bfr[nt][1] = Bcur[(kr + 4) * BST + nc];
            }
#pragma unroll
            for (int mt = 0; mt < 4; mt++)
#pragma unroll
                for (int nt = 0; nt < 4; nt++) {
                    asm volatile(
                        "mma.sync.aligned.m16n8k8.row.col.f32.tf32.tf32.f32 "
                        "{%0,%1,%2,%3}, {%4,%5,%6,%7}, {%8,%9}, {%0,%1,%2,%3};"
                        : "+f"(acc[mt][nt][0]), "+f"(acc[mt][nt][1]),
                          "+f"(acc[mt][nt][2]), "+f"(acc[mt][nt][3])
                        : "r"(a[mt][0]), "r"(a[mt][1]), "r"(a[mt][2]), "r"(a[mt][3]),
                          "r"(bfr[nt][0]), "r"(bfr[nt][1]));
                }
        }
        if (nxt < niter) {
            unsigned* Anx = Asb[nxt & 1];
            unsigned* Bnx = Bsb[nxt & 1];
#pragma unroll
            for (int i = 0; i < 4; i++) {
                unsigned* d = &Anx[aRow * AST + aCol + i * 4];
                d[0] = f2tf32(ra[i].x); d[1] = f2tf32(ra[i].y);
                d[2] = f2tf32(ra[i].z); d[3] = f2tf32(ra[i].w);
                unsigned* e = &Bnx[bRow * BST + bCol + i * 4];
                e[0] = f2tf32(rb[i].x); e[1] = f2tf32(rb[i].y);
                e[2] = f2tf32(rb[i].z); e[3] = f2tf32(rb[i].w);
            }
            __syncthreads();
        }
    }

#pragma unroll
    for (int mt = 0; mt < 4; mt++) {
#pragma unroll
        for (int nt = 0; nt < 4; nt++) {
            int row = brow + wm + mt * 16 + grp;
            int col = bcol + wn + nt * 8 + thr * 2;
            float2 v0 = {acc[mt][nt][0], acc[mt][nt][1]};
            float2 v1 = {acc[mt][nt][2], acc[mt][nt][3]};
            *(float2*)(C + (size_t)row * N + col) = v0;
            *(float2*)(C + (size_t)(row + 8) * N + col) = v1;
        }
    }
}

// ---------------- conv + LN + biases + l2norm, float4 version ----------------
// 192 threads/block, 1 block per pixel; thread t owns channels 4t..4t+3
__global__ __launch_bounds__(192) void conv_ln_kernel(
    const float* __restrict__ qkv, const float* __restrict__ wdw,
    const float* __restrict__ ln_g, const float* __restrict__ ln_b,
    const float* __restrict__ q_bias, const float* __restrict__ v_bias,
    const float* __restrict__ logit_scale,
    float* __restrict__ qn, float* __restrict__ kn, float* __restrict__ vv) {
    int p = blockIdx.x;
    int b = p >> 14, y = (p >> 7) & 127, x = p & 127;
    int t = threadIdx.x;
    int c = t << 2;
    float ax = 0.0f, ay = 0.0f, az = 0.0f, aw = 0.0f;
#pragma unroll
    for (int dy = -1; dy <= 1; dy++) {
        int yy = y + dy;
        if ((unsigned)yy >= (unsigned)HH) continue;
#pragma unroll
        for (int dx = -1; dx <= 1; dx++) {
            int xx = x + dx;
            if ((unsigned)xx >= (unsigned)WW) continue;
            float4 v = *(const float4*)&qkv[(size_t)(((b << 7) | yy) << 7 | xx) * C3 + c];
            float4 wv = *(const float4*)&wdw[((dy + 1) * 3 + (dx + 1)) * C3 + c];
            ax = fmaf(v.x, wv.x, ax); ay = fmaf(v.y, wv.y, ay);
            az = fmaf(v.z, wv.z, az); aw = fmaf(v.w, wv.w, aw);
        }
    }
    float s  = ax + ay + az + aw;
    float s2 = ax * ax + ay * ay + az * az + aw * aw;
#pragma unroll
    for (int o = 16; o; o >>= 1) {
        s  += __shfl_xor_sync(0xffffffffu, s, o);
        s2 += __shfl_xor_sync(0xffffffffu, s2, o);
    }
    __shared__ float ws[6], ws2[6];
    __shared__ float s_mu, s_rstd;
    int lane = t & 31, wrp = t >> 5;
    if (lane == 0) { ws[wrp] = s; ws2[wrp] = s2; }
    __syncthreads();
    if (t < 8) {
        float a1 = (t < 6) ? ws[t]  : 0.0f;
        float a2 = (t < 6) ? ws2[t] : 0.0f;
#pragma unroll
        for (int o = 4; o; o >>= 1) {
            a1 += __shfl_xor_sync(0x000000ffu, a1, o);
            a2 += __shfl_xor_sync(0x000000ffu, a2, o);
        }
        if (t == 0) {
            float mu = a1 * (1.0f / 768.0f);
            float var = a2 * (1.0f / 768.0f) - mu * mu;
            s_mu = mu;
            s_rstd = rsqrtf(var + 1e-5f);
        }
    }
    __syncthreads();
    float4 g  = *(const float4*)&ln_g[c];
    float4 bb = *(const float4*)&ln_b[c];
    float mu = s_mu, rstd = s_rstd;
    float vx = (ax - mu) * rstd * g.x + bb.x;
    float vy = (ay - mu) * rstd * g.y + bb.y;
    float vz = (az - mu) * rstd * g.z + bb.z;
    float vw = (aw - mu) * rstd * g.w + bb.w;

    if (t < 64) {
        float4 qb = *(const float4*)&q_bias[c];
        vx += qb.x; vy += qb.y; vz += qb.z; vw += qb.w;
        float ss = vx * vx + vy * vy + vz * vz + vw * vw;
        ss += __shfl_xor_sync(0xffffffffu, ss, 1);
        ss += __shfl_xor_sync(0xffffffffu, ss, 2);
        ss += __shfl_xor_sync(0xffffffffu, ss, 4);
        float rn = rsqrtf(fmaxf(ss, 1.55e-5f));
        rn *= __expf(fminf(logit_scale[t >> 3], 4.6051701859880914f));
        float4 o = {vx * rn, vy * rn, vz * rn, vw * rn};
        *(float4*)&qn[(size_t)p * CH + c] = o;
    } else if (t < 128) {
        float ss = vx * vx + vy * vy + vz * vz + vw * vw;
        ss += __shfl_xor_sync(0xffffffffu, ss, 1);
        ss += __shfl_xor_sync(0xffffffffu, ss, 2);
        ss += __shfl_xor_sync(0xffffffffu, ss, 4);
        float rn = rsqrtf(fmaxf(ss, 1.55e-5f));
        float4 o = {vx * rn, vy * rn, vz * rn, vw * rn};
        *(float4*)&kn[(size_t)p * CH + (c - 256)] = o;
    } else {
        float4 vb = *(const float4*)&v_bias[c - 512];
        float4 o = {vx + vb.x, vy + vb.y, vz + vb.z, vw + vb.w};
        *(float4*)&vv[(size_t)p * CH + (c - 512)] = o;
    }
}

// ---------------- attention (unchanged from R2) ----------------
constexpr int SM_QS   = 0;
constexpr int SM_KS   = SM_QS + 32 * 64;
constexpr int SM_VS   = SM_KS + 32 * 128;
constexpr int SM_SP   = SM_VS + 128 * 36;
constexpr int SM_BSM  = SM_SP + 128 * 68;
constexpr int SM_LRED = SM_BSM + NREL;
constexpr int SM_LFIN = SM_LRED + 32 * 65;
constexpr int SM_TOT  = SM_LFIN + 64;

__global__ __launch_bounds__(256, 2) void attn_kernel(
    const float* __restrict__ qn, const float* __restrict__ kn,
    const float* __restrict__ vv, const float* __restrict__ btab,
    const float* __restrict__ logit_scale, float* __restrict__ out) {
    extern __shared__ float sm[];
    float* Qs   = sm + SM_QS;
    float* Ks   = sm + SM_KS;
    float* Vs   = sm + SM_VS;
    float* Sp   = sm + SM_SP;
    float* bsm  = sm + SM_BSM;
    float* lred = sm + SM_LRED;
    float* lfin = sm + SM_LFIN;

    int w = blockIdx.x, h = blockIdx.y;
    int b = w >> 8, wr = (w >> 4) & 15, wc = w & 15;
    int t = threadIdx.x;
    float bound = __expf(fminf(logit_scale[h], 4.6051701859880914f)) + 16.0f;

    for (int i = t; i < NREL; i += 256) bsm[i] = btab[i * HEADS + h];

    {
        int qq = t & 63, d0 = (t >> 6) << 3;
        int qi = qq >> 3, qj = qq & 7;
        int py = wr * 8 + qi, px = wc * 8 + qj;
        const float* qp = qn + (size_t)(((b << 7) | py) << 7 | px) * CH + h * HD + d0;
        float4 a = *(const float4*)qp;
        float4 bq = *(const float4*)(qp + 4);
        Qs[(d0 + 0) * 64 + qq] = a.x;  Qs[(d0 + 1) * 64 + qq] = a.y;
        Qs[(d0 + 2) * 64 + qq] = a.z;  Qs[(d0 + 3) * 64 + qq] = a.w;
        Qs[(d0 + 4) * 64 + qq] = bq.x; Qs[(d0 + 5) * 64 + qq] = bq.y;
        Qs[(d0 + 6) * 64 + qq] = bq.z; Qs[(d0 + 7) * 64 + qq] = bq.w;
    }

    int qgA = t & 7, kgA = t >> 3;
    int qgB = t & 7, dg = (t >> 3) & 7, ks = t >> 6;

    int qoff[8];
#pragma unroll
    for (int i = 0; i < 8; i++) {
        int qq = (i < 4) ? (qgA * 4 + i) : (32 + qgA * 4 + (i - 4));
        qoff[i] = (qq >> 3) * 23 + (qq & 7);
    }

    float O[8][4];
#pragma unroll
    for (int i = 0; i < 8; i++)
#pragma unroll
        for (int j = 0; j < 4; j++) O[i][j] = 0.0f;
    float lacc[8];
#pragma unroll
    for (int i = 0; i < 8; i++) lacc[i] = 0.0f;

    for (int c0 = 0; c0 < 2; c0++) {
        __syncthreads();
        {
            int j = t & 127, d1 = (t >> 7) << 4;
            int jg = (c0 << 7) + j;
            int kr = jg >> 4, kc = jg & 15;
            int gy = wr * 8 - 4 + kr, gx = wc * 8 - 4 + kc;
            float4 k0 = {0,0,0,0}, k1 = {0,0,0,0}, k2 = {0,0,0,0}, k3 = {0,0,0,0};
            float4 v0 = {0,0,0,0}, v1 = {0,0,0,0}, v2 = {0,0,0,0}, v3 = {0,0,0,0};
            if ((unsigned)gy < 128u && (unsigned)gx < 128u) {
                size_t gb = (size_t)(((b << 7) | gy) << 7 | gx) * CH + h * HD + d1;
                k0 = *(const float4*)(kn + gb);      k1 = *(const float4*)(kn + gb + 4);
                k2 = *(const float4*)(kn + gb + 8);  k3 = *(const float4*)(kn + gb + 12);
                v0 = *(const float4*)(vv + gb);      v1 = *(const float4*)(vv + gb + 4);
                v2 = *(const float4*)(vv + gb + 8);  v3 = *(const float4*)(vv + gb + 12);
            }
            Ks[(d1 + 0) * 128 + j] = k0.x;  Ks[(d1 + 1) * 128 + j] = k0.y;
            Ks[(d1 + 2) * 128 + j] = k0.z;  Ks[(d1 + 3) * 128 + j] = k0.w;
            Ks[(d1 + 4) * 128 + j] = k1.x;  Ks[(d1 + 5) * 128 + j] = k1.y;
            Ks[(d1 + 6) * 128 + j] = k1.z;  Ks[(d1 + 7) * 128 + j] = k1.w;
            Ks[(d1 + 8) * 128 + j] = k2.x;  Ks[(d1 + 9) * 128 + j] = k2.y;
            Ks[(d1 +10) * 128 + j] = k2.z;  Ks[(d1 +11) * 128 + j] = k2.w;
            Ks[(d1 +12) * 128 + j] = k3.x;  Ks[(d1 +13) * 128 + j] = k3.y;
            Ks[(d1 +14) * 128 + j] = k3.z;  Ks[(d1 +15) * 128 + j] = k3.w;
            float* vp = &Vs[j * 36 + d1];
            *(float4*)(vp + 0) = v0; *(float4*)(vp + 4)  = v1;
            *(float4*)(vp + 8) = v2; *(float4*)(vp + 12) = v3;
        }
        __syncthreads();

        float acc[8][4];
#pragma unroll
        for (int i = 0; i < 8; i++)
#pragma unroll
            for (int j = 0; j < 4; j++) acc[i][j] = 0.0f;
#pragma unroll 8
        for (int kk = 0; kk < 32; kk++) {
            float4 ra0 = *(const float4*)&Qs[kk * 64 + qgA * 4];
            float4 ra1 = *(const float4*)&Qs[kk * 64 + 32 + qgA * 4];
            float4 rb  = *(const float4*)&Ks[kk * 128 + kgA * 4];
            float a[8] = {ra0.x, ra0.y, ra0.z, ra0.w, ra1.x, ra1.y, ra1.z, ra1.w};
            float bk[4] = {rb.x, rb.y, rb.z, rb.w};
#pragma unroll
            for (int i = 0; i < 8; i++)
#pragma unroll
                for (int j = 0; j < 4; j++) acc[i][j] = fmaf(a[i], bk[j], acc[i][j]);
        }
#pragma unroll
        for (int j = 0; j < 4; j++) {
            int krow = kgA * 4 + j;
            int jg = (c0 << 7) + krow;
            int base = (15 - (jg >> 4)) * 23 + (15 - (jg & 15));
            float p[8];
#pragma unroll
            for (int i = 0; i < 8; i++) {
                p[i] = __expf(acc[i][j] - bound + bsm[base + qoff[i]]);
                lacc[i] += p[i];
            }
            float4 p03 = {p[0], p[1], p[2], p[3]};
            float4 p47 = {p[4], p[5], p[6], p[7]};
            *(float4*)&Sp[krow * 68 + qgA * 4]      = p03;
            *(float4*)&Sp[krow * 68 + 32 + qgA * 4] = p47;
        }
        __syncthreads();

#pragma unroll 4
        for (int jj = 0; jj < 32; jj++) {
            int jr = ks * 32 + jj;
            float4 p0 = *(const float4*)&Sp[jr * 68 + qgB * 4];
            float4 p1 = *(const float4*)&Sp[jr * 68 + 32 + qgB * 4];
            float4 v4 = *(const float4*)&Vs[jr * 36 + dg * 4];
            float p[8] = {p0.x, p0.y, p0.z, p0.w, p1.x, p1.y, p1.z, p1.w};
            float vr[4] = {v4.x, v4.y, v4.z, v4.w};
#pragma unroll
            for (int i = 0; i < 8; i++)
#pragma unroll
                for (int d = 0; d < 4; d++) O[i][d] = fmaf(p[i], vr[d], O[i][d]);
        }
    }
    __syncthreads();

#pragma unroll
    for (int i = 0; i < 8; i++) {
        int qq = (i < 4) ? (qgA * 4 + i) : (32 + qgA * 4 + (i - 4));
        lred[kgA * 65 + qq] = lacc[i];
    }
    float* Osm = Sp;
#pragma unroll
    for (int i = 0; i < 8; i++) {
        int qq = (i < 4) ? (qgB * 4 + i) : (32 + qgB * 4 + (i - 4));
#pragma unroll
        for (int d = 0; d < 4; d++)
            Osm[(ks * 64 + qq) * 33 + dg * 4 + d] = O[i][d];
    }
    __syncthreads();
    if (t < 64) {
        float ssum = 0.0f;
#pragma unroll
        for (int g = 0; g < 32; g++) ssum += lred[g * 65 + t];
        lfin[t] = 1.0f / ssum;
    }
    __syncthreads();

    {
        int qq = t >> 2, d0 = (t & 3) << 3;
        float inv = lfin[qq];
        float o[8];
#pragma unroll
        for (int d = 0; d < 8; d++) {
            o[d] = (Osm[(qq) * 33 + d0 + d] + Osm[(64 + qq) * 33 + d0 + d] +
                    Osm[(128 + qq) * 33 + d0 + d] + Osm[(192 + qq) * 33 + d0 + d]) * inv;
        }
        int qi = qq >> 3, qj = qq & 7;
        int py = wr * 8 + qi, px = wc * 8 + qj;
        float* op = out + (size_t)(((b << 7) | py) << 7 | px) * CH + h * HD + d0;
        float4 o0 = {o[0], o[1], o[2], o[3]};
        float4 o1 = {o[4], o[5], o[6], o[7]};
        *(float4*)op = o0;
        *(float4*)(op + 4) = o1;
    }
}

// ---------------- launch ----------------
extern "C" void kernel_launch(void* const* d_in, const int* in_sizes, int n_in,
                              void* d_out, int out_size) {
    const float* x           = (const float*)d_in[0];
    const float* w_qkv       = (const float*)d_in[1];
    const float* w_dw        = (const float*)d_in[2];
    const float* ln_g        = (const float*)d_in[3];
    const float* ln_b        = (const float*)d_in[4];
    const float* q_bias      = (const float*)d_in[5];
    const float* v_bias      = (const float*)d_in[6];
    const float* logit_scale = (const float*)d_in[7];
    const float* cpb_w1      = (const float*)d_in[8];
    const float* cpb_b1      = (const float*)d_in[9];
    const float* cpb_w2      = (const float*)d_in[10];
    const float* w_proj      = (const float*)d_in[11];
    float* out = (float*)d_out;

    float *qkv, *qn, *kn, *vv, *att, *btab;
    cudaGetSymbolAddress((void**)&qkv,  g_qkv);
    cudaGetSymbolAddress((void**)&qn,   g_qn);
    cudaGetSymbolAddress((void**)&kn,   g_kn);
    cudaGetSymbolAddress((void**)&vv,   g_v);
    cudaGetSymbolAddress((void**)&att,  g_att);
    cudaGetSymbolAddress((void**)&btab, g_btab);

    int smem_attn = SM_TOT * 4;
    cudaFuncSetAttribute(attn_kernel, cudaFuncAttributeMaxDynamicSharedMemorySize, smem_attn);
    cudaFuncSetAttribute(mma_gemm, cudaFuncAttributeMaxDynamicSharedMemorySize, GEMM_SMEM);

    cpb_kernel<<<NREL, 256>>>(cpb_w1, cpb_b1, cpb_w2, btab);
    mma_gemm<<<dim3(C3 / 128, NPIX / 128), 256, GEMM_SMEM>>>(NPIX, C3, CH, x, w_qkv, qkv);
    conv_ln_kernel<<<NPIX, 192>>>(qkv, w_dw, ln_g, ln_b, q_bias, v_bias, logit_scale,
                                  qn, kn, vv);
    attn_kernel<<<dim3(512, 8), 256, smem_attn>>>(qn, kn, vv, btab, logit_scale, att);
    mma_gemm<<<dim3(CH / 128, NPIX / 128), 256, GEMM_SMEM>>>(NPIX, CH, CH, att, w_proj, out);
}

// round 5
// speedup vs baseline: 2.0368x; 1.0119x over previous
#include <cuda_runtime.h>
#include <math.h>

// ---------------- problem constants ----------------
constexpr int BATCH = 2, HH = 128, WW = 128, CH = 256;
constexpr int HEADS = 8, HD = 32;
constexpr int NPIX = BATCH * HH * WW;   // 32768
constexpr int C3 = 3 * CH;              // 768
constexpr int NREL = 23 * 23;           // 529

// ---------------- device scratch (allocation-free) ----------------
__device__ float g_qkv[NPIX * C3];
__device__ float g_qn [NPIX * CH];
__device__ float g_kn [NPIX * CH];
__device__ float g_v  [NPIX * CH];
__device__ float g_att[NPIX * CH];
__device__ float g_btab[NREL * HEADS];

// ---------------- CPB relative-bias MLP ----------------
__device__ __forceinline__ float relcoord(int r) {
    float cs = (float)(r - 11) * (8.0f / 7.0f);
    float a = log1pf(fabsf(cs)) * (1.0f / 2.0794415416798357f);
    return cs > 0.0f ? a : (cs < 0.0f ? -a : 0.0f);
}

__global__ void cpb_kernel(const float* __restrict__ w1, const float* __restrict__ b1,
                           const float* __restrict__ w2, float* __restrict__ btab) {
    int i = blockIdx.x;
    float y0 = relcoord(i / 23), y1 = relcoord(i % 23);
    int t = threadIdx.x;
    float part[HEADS];
#pragma unroll
    for (int hh = 0; hh < HEADS; hh++) part[hh] = 0.0f;
    for (int j = t; j < 512; j += 256) {
        float hv = fmaf(y0, w1[j], fmaf(y1, w1[512 + j], b1[j]));
        hv = fmaxf(hv, 0.0f);
#pragma unroll
        for (int hh = 0; hh < HEADS; hh++) part[hh] = fmaf(hv, w2[j * HEADS + hh], part[hh]);
    }
#pragma unroll
    for (int hh = 0; hh < HEADS; hh++)
#pragma unroll
        for (int o = 16; o; o >>= 1) part[hh] += __shfl_xor_sync(0xffffffffu, part[hh], o);
    __shared__ float sm[HEADS][8];
    int lane = t & 31, wrp = t >> 5;
    if (lane == 0)
        for (int hh = 0; hh < HEADS; hh++) sm[hh][wrp] = part[hh];
    __syncthreads();
    if (t < HEADS) {
        float ssum = 0.0f;
        for (int k = 0; k < 8; k++) ssum += sm[t][k];
        btab[i * HEADS + t] = 16.0f / (1.0f + expf(-ssum));
    }
}

// ---------------- tf32 helpers ----------------
__device__ __forceinline__ unsigned f2tf32(float x) {
    unsigned r;
    asm("cvt.rna.tf32.f32 %0, %1;" : "=r"(r) : "f"(x));
    return r;
}
__device__ __forceinline__ void split_tf32(float x, unsigned& hi, unsigned& lo) {
    hi = f2tf32(x);
    lo = f2tf32(x - __uint_as_float(hi));
}
#define MMA_TF32(C, A0, A1, A2, A3, B0, B1)                                    \
    asm volatile(                                                              \
        "mma.sync.aligned.m16n8k8.row.col.f32.tf32.tf32.f32 "                  \
        "{%0,%1,%2,%3}, {%4,%5,%6,%7}, {%8,%9}, {%0,%1,%2,%3};"                \
        : "+f"((C)[0]), "+f"((C)[1]), "+f"((C)[2]), "+f"((C)[3])               \
        : "r"(A0), "r"(A1), "r"(A2), "r"(A3), "r"(B0), "r"(B1))

// ---------------- tf32 tensor-core GEMM, double-buffered (unchanged R4) ----------------
constexpr int GBM = 128, GBN = 128, GBK = 32;
constexpr int AST = GBK + 4;   // 36
constexpr int BST = GBN + 8;   // 136
constexpr int ABUF = GBM * AST;
constexpr int BBUF = GBK * BST;
constexpr int GEMM_SMEM = 2 * (ABUF + BBUF) * 4;

__global__ __launch_bounds__(256) void mma_gemm(int M, int N, int K,
                                                const float* __restrict__ A,
                                                const float* __restrict__ B,
                                                float* __restrict__ C) {
    extern __shared__ unsigned smu[];
    unsigned* Asb[2] = {smu, smu + ABUF};
    unsigned* Bsb[2] = {smu + 2 * ABUF, smu + 2 * ABUF + BBUF};

    int tid = threadIdx.x;
    int warp = tid >> 5, lane = tid & 31;
    int wm = (warp & 1) * 64, wn = (warp >> 1) * 32;
    int brow = blockIdx.y * GBM, bcol = blockIdx.x * GBN;
    int grp = lane >> 2, thr = lane & 3;

    float acc[4][4][4];
#pragma unroll
    for (int i = 0; i < 4; i++)
#pragma unroll
        for (int j = 0; j < 4; j++)
#pragma unroll
            for (int r = 0; r < 4; r++) acc[i][j][r] = 0.0f;

    int aRow = tid >> 1, aCol = (tid & 1) << 4;
    int bRow = tid >> 3, bCol = (tid & 7) << 4;

    const float* Ap = A + (size_t)(brow + aRow) * K + aCol;
    const float* Bp = B + (size_t)bRow * N + bcol + bCol;

    float4 ra[4], rb[4];
    int niter = K / GBK;

#pragma unroll
    for (int i = 0; i < 4; i++) ra[i] = *(const float4*)(Ap + i * 4);
#pragma unroll
    for (int i = 0; i < 4; i++) rb[i] = *(const float4*)(Bp + i * 4);
#pragma unroll
    for (int i = 0; i < 4; i++) {
        unsigned* d = &Asb[0][aRow * AST + aCol + i * 4];
        d[0] = f2tf32(ra[i].x); d[1] = f2tf32(ra[i].y);
        d[2] = f2tf32(ra[i].z); d[3] = f2tf32(ra[i].w);
        unsigned* e = &Bsb[0][bRow * BST + bCol + i * 4];
        e[0] = f2tf32(rb[i].x); e[1] = f2tf32(rb[i].y);
        e[2] = f2tf32(rb[i].z); e[3] = f2tf32(rb[i].w);
    }
    __syncthreads();

    for (int iter = 0; iter < niter; iter++) {
        int nxt = iter + 1;
        if (nxt < niter) {
#pragma unroll
            for (int i = 0; i < 4; i++) ra[i] = *(const float4*)(Ap + nxt * GBK + i * 4);
#pragma unroll
            for (int i = 0; i < 4; i++) rb[i] = *(const float4*)(Bp + (size_t)nxt * GBK * N + i * 4);
        }
        const unsigned* Acur = Asb[iter & 1];
        const unsigned* Bcur = Bsb[iter & 1];
#pragma unroll
        for (int kstep = 0; kstep < 4; kstep++) {
            int kb = kstep * 8;
            unsigned a[4][4], bfr[4][2];
#pragma unroll
            for (int mt = 0; mt < 4; mt++) {
                int r0 = wm + mt * 16 + grp;
                int ca = kb + thr;
                a[mt][0] = Acur[r0 * AST + ca];
                a[mt][1] = Acur[(r0 + 8) * AST + ca];
                a[mt][2] = Acur[r0 * AST + ca + 4];
                a[mt][3] = Acur[(r0 + 8) * AST + ca + 4];
            }
#pragma unroll
            for (int nt = 0; nt < 4; nt++) {
                int kr = kb + thr;
                int nc = wn + nt * 8 + grp;
                bfr[nt][0] = Bcur[kr * BST + nc];
                bfr[nt][1] = Bcur[(kr + 4) * BST + nc];
            }
#pragma unroll
            for (int mt = 0; mt < 4; mt++)
#pragma unroll
                for (int nt = 0; nt < 4; nt++)
                    MMA_TF32(acc[mt][nt], a[mt][0], a[mt][1], a[mt][2], a[mt][3],
                             bfr[nt][0], bfr[nt][1]);
        }
        if (nxt < niter) {
            unsigned* Anx = Asb[nxt & 1];
            unsigned* Bnx = Bsb[nxt & 1];
#pragma unroll
            for (int i = 0; i < 4; i++) {
                unsigned* d = &Anx[aRow * AST + aCol + i * 4];
                d[0] = f2tf32(ra[i].x); d[1] = f2tf32(ra[i].y);
                d[2] = f2tf32(ra[i].z); d[3] = f2tf32(ra[i].w);
                unsigned* e = &Bnx[bRow * BST + bCol + i * 4];
                e[0] = f2tf32(rb[i].x); e[1] = f2tf32(rb[i].y);
                e[2] = f2tf32(rb[i].z); e[3] = f2tf32(rb[i].w);
            }
            __syncthreads();
        }
    }

#pragma unroll
    for (int mt = 0; mt < 4; mt++) {
#pragma unroll
        for (int nt = 0; nt < 4; nt++) {
            int row = brow + wm + mt * 16 + grp;
            int col = bcol + wn + nt * 8 + thr * 2;
            float2 v0 = {acc[mt][nt][0], acc[mt][nt][1]};
            float2 v1 = {acc[mt][nt][2], acc[mt][nt][3]};
            *(float2*)(C + (size_t)row * N + col) = v0;
            *(float2*)(C + (size_t)(row + 8) * N + col) = v1;
        }
    }
}

// ---------------- conv + LN + biases + l2norm (unchanged R4) ----------------
__global__ __launch_bounds__(192) void conv_ln_kernel(
    const float* __restrict__ qkv, const float* __restrict__ wdw,
    const float* __restrict__ ln_g, const float* __restrict__ ln_b,
    const float* __restrict__ q_bias, const float* __restrict__ v_bias,
    const float* __restrict__ logit_scale,
    float* __restrict__ qn, float* __restrict__ kn, float* __restrict__ vv) {
    int p = blockIdx.x;
    int b = p >> 14, y = (p >> 7) & 127, x = p & 127;
    int t = threadIdx.x;
    int c = t << 2;
    float ax = 0.0f, ay = 0.0f, az = 0.0f, aw = 0.0f;
#pragma unroll
    for (int dy = -1; dy <= 1; dy++) {
        int yy = y + dy;
        if ((unsigned)yy >= (unsigned)HH) continue;
#pragma unroll
        for (int dx = -1; dx <= 1; dx++) {
            int xx = x + dx;
            if ((unsigned)xx >= (unsigned)WW) continue;
            float4 v = *(const float4*)&qkv[(size_t)(((b << 7) | yy) << 7 | xx) * C3 + c];
            float4 wv = *(const float4*)&wdw[((dy + 1) * 3 + (dx + 1)) * C3 + c];
            ax = fmaf(v.x, wv.x, ax); ay = fmaf(v.y, wv.y, ay);
            az = fmaf(v.z, wv.z, az); aw = fmaf(v.w, wv.w, aw);
        }
    }
    float s  = ax + ay + az + aw;
    float s2 = ax * ax + ay * ay + az * az + aw * aw;
#pragma unroll
    for (int o = 16; o; o >>= 1) {
        s  += __shfl_xor_sync(0xffffffffu, s, o);
        s2 += __shfl_xor_sync(0xffffffffu, s2, o);
    }
    __shared__ float ws[6], ws2[6];
    __shared__ float s_mu, s_rstd;
    int lane = t & 31, wrp = t >> 5;
    if (lane == 0) { ws[wrp] = s; ws2[wrp] = s2; }
    __syncthreads();
    if (t < 8) {
        float a1 = (t < 6) ? ws[t]  : 0.0f;
        float a2 = (t < 6) ? ws2[t] : 0.0f;
#pragma unroll
        for (int o = 4; o; o >>= 1) {
            a1 += __shfl_xor_sync(0x000000ffu, a1, o);
            a2 += __shfl_xor_sync(0x000000ffu, a2, o);
        }
        if (t == 0) {
            float mu = a1 * (1.0f / 768.0f);
            float var = a2 * (1.0f / 768.0f) - mu * mu;
            s_mu = mu;
            s_rstd = rsqrtf(var + 1e-5f);
        }
    }
    __syncthreads();
    float4 g  = *(const float4*)&ln_g[c];
    float4 bb = *(const float4*)&ln_b[c];
    float mu = s_mu, rstd = s_rstd;
    float vx = (ax - mu) * rstd * g.x + bb.x;
    float vy = (ay - mu) * rstd * g.y + bb.y;
    float vz = (az - mu) * rstd * g.z + bb.z;
    float vw = (aw - mu) * rstd * g.w + bb.w;

    if (t < 64) {
        float4 qb = *(const float4*)&q_bias[c];
        vx += qb.x; vy += qb.y; vz += qb.z; vw += qb.w;
        float ss = vx * vx + vy * vy + vz * vz + vw * vw;
        ss += __shfl_xor_sync(0xffffffffu, ss, 1);
        ss += __shfl_xor_sync(0xffffffffu, ss, 2);
        ss += __shfl_xor_sync(0xffffffffu, ss, 4);
        float rn = rsqrtf(fmaxf(ss, 1.55e-5f));
        rn *= __expf(fminf(logit_scale[t >> 3], 4.6051701859880914f));
        float4 o = {vx * rn, vy * rn, vz * rn, vw * rn};
        *(float4*)&qn[(size_t)p * CH + c] = o;
    } else if (t < 128) {
        float ss = vx * vx + vy * vy + vz * vz + vw * vw;
        ss += __shfl_xor_sync(0xffffffffu, ss, 1);
        ss += __shfl_xor_sync(0xffffffffu, ss, 2);
        ss += __shfl_xor_sync(0xffffffffu, ss, 4);
        float rn = rsqrtf(fmaxf(ss, 1.55e-5f));
        float4 o = {vx * rn, vy * rn, vz * rn, vw * rn};
        *(float4*)&kn[(size_t)p * CH + (c - 256)] = o;
    } else {
        float4 vb = *(const float4*)&v_bias[c - 512];
        float4 o = {vx + vb.x, vy + vb.y, vz + vb.z, vw + vb.w};
        *(float4*)&vv[(size_t)p * CH + (c - 512)] = o;
    }
}

// ---------------- attention: split-tf32 warp-MMA flash kernel ----------------
// grid (512 windows, 8 heads), 256 threads = 8 warps. 4 chunks of 64 keys.
// smem float offsets:
constexpr int A_QSH = 0;                 // [64][36]
constexpr int A_QSL = A_QSH + 64 * 36;   // [64][36]
constexpr int A_KSH = A_QSL + 64 * 36;   // [32][72]  (dim-major, transposed)
constexpr int A_KSL = A_KSH + 32 * 72;
constexpr int A_VSH = A_KSL + 32 * 72;   // [64][40]  (key-major)
constexpr int A_VSL = A_VSH + 64 * 40;
constexpr int A_SP  = A_VSL + 64 * 40;   // [64][68]  P (fp32)
constexpr int A_BSM = A_SP + 64 * 68;    // [529]
constexpr int A_LRD = A_BSM + NREL;      // [4][64]
constexpr int A_LFN = A_LRD + 256;       // [64]
constexpr int A_TOT = A_LFN + 64;        // 19537 floats = 78148 B

__global__ __launch_bounds__(256, 2) void attn_kernel(
    const float* __restrict__ qn, const float* __restrict__ kn,
    const float* __restrict__ vv, const float* __restrict__ btab,
    const float* __restrict__ logit_scale, float* __restrict__ out) {
    extern __shared__ float sm[];
    float* QsH = sm + A_QSH;  float* QsL = sm + A_QSL;
    float* KsH = sm + A_KSH;  float* KsL = sm + A_KSL;
    float* VsH = sm + A_VSH;  float* VsL = sm + A_VSL;
    float* Sp  = sm + A_SP;
    float* bsm = sm + A_BSM;
    float* lrd = sm + A_LRD;
    float* lfn = sm + A_LFN;

    int w = blockIdx.x, h = blockIdx.y;
    int b = w >> 8, wr = (w >> 4) & 15, wc = w & 15;
    int t = threadIdx.x;
    int warp = t >> 5, lane = t & 31, grp = lane >> 2, thr = lane & 3;
    float bound = __expf(fminf(logit_scale[h], 4.6051701859880914f)) + 16.0f;

    for (int i = t; i < NREL; i += 256) bsm[i] = btab[i * HEADS + h];

    // stage Q (pre-split hi/lo tf32), row-major [64][36]
    {
        int row = t & 63, d0 = (t >> 6) << 3;
        int py = wr * 8 + (row >> 3), px = wc * 8 + (row & 7);
        const float* qp = qn + (size_t)(((b << 7) | py) << 7 | px) * CH + h * HD + d0;
        float4 a = *(const float4*)qp;
        float4 bq = *(const float4*)(qp + 4);
        float v[8] = {a.x, a.y, a.z, a.w, bq.x, bq.y, bq.z, bq.w};
#pragma unroll
        for (int i = 0; i < 8; i++) {
            unsigned hb, lb;
            split_tf32(v[i], hb, lb);
            QsH[row * 36 + d0 + i] = __uint_as_float(hb);
            QsL[row * 36 + d0 + i] = __uint_as_float(lb);
        }
    }

    // phase-A warp tile: rows wmA..+31, cols wnA..+15 (of 64-key chunk)
    int wmA = (warp & 1) * 32, wnA = (warp >> 1) * 16;
    // phase-B warp tile: rows mB*16..+15, dims nB*16..+15
    int mB = warp & 3, nB = warp >> 2;

    float oacc[2][4];
#pragma unroll
    for (int nt = 0; nt < 2; nt++)
#pragma unroll
        for (int r = 0; r < 4; r++) oacc[nt][r] = 0.0f;
    float rs[4] = {0.0f, 0.0f, 0.0f, 0.0f};

    for (int c0 = 0; c0 < 4; c0++) {
        __syncthreads();   // prev PV done reading Sp/Vs; Q staged (first iter)
        // ---- stage K (transposed, split) and V (split) for 64-key chunk ----
        {
            int j = t & 63, d1 = (t >> 6) << 3;
            int jg = (c0 << 6) + j;
            int kr = jg >> 4, kc = jg & 15;
            int gy = wr * 8 - 4 + kr, gx = wc * 8 - 4 + kc;
            float kv[8] = {0, 0, 0, 0, 0, 0, 0, 0};
            float vvv[8] = {0, 0, 0, 0, 0, 0, 0, 0};
            if ((unsigned)gy < 128u && (unsigned)gx < 128u) {
                size_t gb = (size_t)(((b << 7) | gy) << 7 | gx) * CH + h * HD + d1;
                float4 k0 = *(const float4*)(kn + gb), k1 = *(const float4*)(kn + gb + 4);
                float4 v0 = *(const float4*)(vv + gb), v1 = *(const float4*)(vv + gb + 4);
                kv[0] = k0.x; kv[1] = k0.y; kv[2] = k0.z; kv[3] = k0.w;
                kv[4] = k1.x; kv[5] = k1.y; kv[6] = k1.z; kv[7] = k1.w;
                vvv[0] = v0.x; vvv[1] = v0.y; vvv[2] = v0.z; vvv[3] = v0.w;
                vvv[4] = v1.x; vvv[5] = v1.y; vvv[6] = v1.z; vvv[7] = v1.w;
            }
#pragma unroll
            for (int i = 0; i < 8; i++) {
                unsigned hb, lb;
                split_tf32(kv[i], hb, lb);
                KsH[(d1 + i) * 72 + j] = __uint_as_float(hb);
                KsL[(d1 + i) * 72 + j] = __uint_as_float(lb);
            }
            float vh[8], vl[8];
#pragma unroll
            for (int i = 0; i < 8; i++) {
                unsigned hb, lb;
                split_tf32(vvv[i], hb, lb);
                vh[i] = __uint_as_float(hb);
                vl[i] = __uint_as_float(lb);
            }
            *(float4*)&VsH[j * 40 + d1]     = *(float4*)&vh[0];
            *(float4*)&VsH[j * 40 + d1 + 4] = *(float4*)&vh[4];
            *(float4*)&VsL[j * 40 + d1]     = *(float4*)&vl[0];
            *(float4*)&VsL[j * 40 + d1 + 4] = *(float4*)&vl[4];
        }
        __syncthreads();

        // ---- QK^T: S[32x16] per warp, split-tf32 (3 mma each) ----
        float acc[2][2][4];
#pragma unroll
        for (int mt = 0; mt < 2; mt++)
#pragma unroll
            for (int nt = 0; nt < 2; nt++)
#pragma unroll
                for (int r = 0; r < 4; r++) acc[mt][nt][r] = 0.0f;

        const unsigned* QH = (const unsigned*)QsH;
        const unsigned* QL = (const unsigned*)QsL;
        const unsigned* KH = (const unsigned*)KsH;
        const unsigned* KL = (const unsigned*)KsL;
#pragma unroll
        for (int ks = 0; ks < 4; ks++) {
            int kb = ks * 8;
            unsigned aH[2][4], aL[2][4], bH[2][2], bL[2][2];
#pragma unroll
            for (int mt = 0; mt < 2; mt++) {
                int r0 = wmA + mt * 16 + grp;
                int ca = kb + thr;
                aH[mt][0] = QH[r0 * 36 + ca];       aH[mt][1] = QH[(r0 + 8) * 36 + ca];
                aH[mt][2] = QH[r0 * 36 + ca + 4];   aH[mt][3] = QH[(r0 + 8) * 36 + ca + 4];
                aL[mt][0] = QL[r0 * 36 + ca];       aL[mt][1] = QL[(r0 + 8) * 36 + ca];
                aL[mt][2] = QL[r0 * 36 + ca + 4];   aL[mt][3] = QL[(r0 + 8) * 36 + ca + 4];
            }
#pragma unroll
            for (int nt = 0; nt < 2; nt++) {
                int nc = wnA + nt * 8 + grp;
                bH[nt][0] = KH[(kb + thr) * 72 + nc];
                bH[nt][1] = KH[(kb + thr + 4) * 72 + nc];
                bL[nt][0] = KL[(kb + thr) * 72 + nc];
                bL[nt][1] = KL[(kb + thr + 4) * 72 + nc];
            }
#pragma unroll
            for (int mt = 0; mt < 2; mt++)
#pragma unroll
                for (int nt = 0; nt < 2; nt++) {
                    MMA_TF32(acc[mt][nt], aH[mt][0], aH[mt][1], aH[mt][2], aH[mt][3],
                             bH[nt][0], bH[nt][1]);
                    MMA_TF32(acc[mt][nt], aH[mt][0], aH[mt][1], aH[mt][2], aH[mt][3],
                             bL[nt][0], bL[nt][1]);
                    MMA_TF32(acc[mt][nt], aL[mt][0], aL[mt][1], aL[mt][2], aL[mt][3],
                             bH[nt][0], bH[nt][1]);
                }
        }

        // ---- bias + exp + P store + row-sum accum ----
        int cbg = c0 << 6;
#pragma unroll
        for (int mt = 0; mt < 2; mt++) {
            int r0 = wmA + mt * 16 + grp, r1 = r0 + 8;
            int q0 = (r0 >> 3) * 23 + (r0 & 7);
            int q1 = (r1 >> 3) * 23 + (r1 & 7);
#pragma unroll
            for (int nt = 0; nt < 2; nt++) {
                int lc = wnA + nt * 8 + 2 * thr;
                int jg0 = cbg + lc, jg1 = jg0 + 1;
                int b0 = (15 - (jg0 >> 4)) * 23 + (15 - (jg0 & 15));
                int b1 = (15 - (jg1 >> 4)) * 23 + (15 - (jg1 & 15));
                float p00 = __expf(acc[mt][nt][0] - bound + bsm[b0 + q0]);
                float p01 = __expf(acc[mt][nt][1] - bound + bsm[b1 + q0]);
                float p10 = __expf(acc[mt][nt][2] - bound + bsm[b0 + q1]);
                float p11 = __expf(acc[mt][nt][3] - bound + bsm[b1 + q1]);
                rs[mt * 2]     += p00 + p01;
                rs[mt * 2 + 1] += p10 + p11;
                float2 w0 = {p00, p01};
                float2 w1 = {p10, p11};
                *(float2*)&Sp[r0 * 68 + lc] = w0;
                *(float2*)&Sp[r1 * 68 + lc] = w1;
            }
        }
        __syncthreads();

        // ---- PV: O[16x16] per warp, k = 64 keys, split-tf32 ----
        const unsigned* VH = (const unsigned*)VsH;
        const unsigned* VL = (const unsigned*)VsL;
        int ra = mB * 16 + grp;
#pragma unroll
        for (int ks = 0; ks < 8; ks++) {
            int kb = ks * 8;
            float af[4];
            af[0] = Sp[ra * 68 + kb + thr];
            af[1] = Sp[(ra + 8) * 68 + kb + thr];
            af[2] = Sp[ra * 68 + kb + thr + 4];
            af[3] = Sp[(ra + 8) * 68 + kb + thr + 4];
            unsigned ah[4], al[4];
#pragma unroll
            for (int i = 0; i < 4; i++) split_tf32(af[i], ah[i], al[i]);
#pragma unroll
            for (int nt = 0; nt < 2; nt++) {
                int col = nB * 16 + nt * 8 + grp;
                unsigned bh0 = VH[(kb + thr) * 40 + col];
                unsigned bh1 = VH[(kb + thr + 4) * 40 + col];
                unsigned bl0 = VL[(kb + thr) * 40 + col];
                unsigned bl1 = VL[(kb + thr + 4) * 40 + col];
                MMA_TF32(oacc[nt], ah[0], ah[1], ah[2], ah[3], bh0, bh1);
                MMA_TF32(oacc[nt], ah[0], ah[1], ah[2], ah[3], bl0, bl1);
                MMA_TF32(oacc[nt], al[0], al[1], al[2], al[3], bh0, bh1);
            }
        }
    }

    // ---- row-sum reduction ----
#pragma unroll
    for (int i = 0; i < 4; i++) {
        rs[i] += __shfl_xor_sync(0xffffffffu, rs[i], 1);
        rs[i] += __shfl_xor_sync(0xffffffffu, rs[i], 2);
    }
    if (thr == 0) {
#pragma unroll
        for (int mt = 0; mt < 2; mt++) {
#pragma unroll
            for (int hh = 0; hh < 2; hh++) {
                int row = wmA + mt * 16 + hh * 8 + grp;
                lrd[(warp >> 1) * 64 + row] = rs[mt * 2 + hh];
            }
        }
    }
    __syncthreads();
    if (t < 64)
        lfn[t] = 1.0f / (lrd[t] + lrd[64 + t] + lrd[128 + t] + lrd[192 + t]);
    __syncthreads();

    // ---- normalize + write ----
    {
        int r0 = mB * 16 + grp, r1 = r0 + 8;
        float inv0 = lfn[r0], inv1 = lfn[r1];
        int py0 = wr * 8 + (r0 >> 3), px0 = wc * 8 + (r0 & 7);
        int py1 = wr * 8 + (r1 >> 3), px1 = wc * 8 + (r1 & 7);
        float* op0 = out + (size_t)(((b << 7) | py0) << 7 | px0) * CH + h * HD;
        float* op1 = out + (size_t)(((b << 7) | py1) << 7 | px1) * CH + h * HD;
#pragma unroll
        for (int nt = 0; nt < 2; nt++) {
            int col = nB * 16 + nt * 8 + 2 * thr;
            float2 w0 = {oacc[nt][0] * inv0, oacc[nt][1] * inv0};
            float2 w1 = {oacc[nt][2] * inv1, oacc[nt][3] * inv1};
            *(float2*)(op0 + col) = w0;
            *(float2*)(op1 + col) = w1;
        }
    }
}

// ---------------- launch ----------------
extern "C" void kernel_launch(void* const* d_in, const int* in_sizes, int n_in,
                              void* d_out, int out_size) {
    const float* x           = (const float*)d_in[0];
    const float* w_qkv       = (const float*)d_in[1];
    const float* w_dw        = (const float*)d_in[2];
    const float* ln_g        = (const float*)d_in[3];
    const float* ln_b        = (const float*)d_in[4];
    const float* q_bias      = (const float*)d_in[5];
    const float* v_bias      = (const float*)d_in[6];
    const float* logit_scale = (const float*)d_in[7];
    const float* cpb_w1      = (const float*)d_in[8];
    const float* cpb_b1      = (const float*)d_in[9];
    const float* cpb_w2      = (const float*)d_in[10];
    const float* w_proj      = (const float*)d_in[11];
    float* out = (float*)d_out;

    float *qkv, *qn, *kn, *vv, *att, *btab;
    cudaGetSymbolAddress((void**)&qkv,  g_qkv);
    cudaGetSymbolAddress((void**)&qn,   g_qn);
    cudaGetSymbolAddress((void**)&kn,   g_kn);
    cudaGetSymbolAddress((void**)&vv,   g_v);
    cudaGetSymbolAddress((void**)&att,  g_att);
    cudaGetSymbolAddress((void**)&btab, g_btab);

    int smem_attn = A_TOT * 4;
    cudaFuncSetAttribute(attn_kernel, cudaFuncAttributeMaxDynamicSharedMemorySize, smem_attn);
    cudaFuncSetAttribute(mma_gemm, cudaFuncAttributeMaxDynamicSharedMemorySize, GEMM_SMEM);

    cpb_kernel<<<NREL, 256>>>(cpb_w1, cpb_b1, cpb_w2, btab);
    mma_gemm<<<dim3(C3 / 128, NPIX / 128), 256, GEMM_SMEM>>>(NPIX, C3, CH, x, w_qkv, qkv);
    conv_ln_kernel<<<NPIX, 192>>>(qkv, w_dw, ln_g, ln_b, q_bias, v_bias, logit_scale,
                                  qn, kn, vv);
    attn_kernel<<<dim3(512, 8), 256, smem_attn>>>(qn, kn, vv, btab, logit_scale, att);
    mma_gemm<<<dim3(CH / 128, NPIX / 128), 256, GEMM_SMEM>>>(NPIX, CH, CH, att, w_proj, out);
}